// round 10
// baseline (speedup 1.0000x reference)
#include <cuda_runtime.h>
#include <math.h>

#define NMAX 10000
#define EMAX 160000
#define TBL 16384
typedef unsigned long long ull;

// device scratch (no runtime allocation)
__device__ __align__(16) float g_p0[NMAX * 16];
__device__ __align__(16) float g_p1[NMAX * 24];
__device__ float g_z[NMAX];
__device__ float g_expv[EMAX];
__device__ __align__(16) float g_WkT[9216];      // [j*16+c]
__device__ __align__(16) float g_WvT[9216];
__device__ __align__(16) float g_tk[TBL * 16];   // hk(d) table
__device__ __align__(16) float g_tv[TBL * 16];   // hv(d) table

// ---------- packed f32x2 primitives ----------
__device__ __forceinline__ ull pk2(float a) {
    ull r; asm("mov.b64 %0, {%1,%1};" : "=l"(r) : "f"(a)); return r;
}
__device__ __forceinline__ ull pk(float a, float b) {
    ull r; asm("mov.b64 %0, {%1,%2};" : "=l"(r) : "f"(a), "f"(b)); return r;
}
__device__ __forceinline__ float2 upk(ull a) {
    float2 f; asm("mov.b64 {%0,%1}, %2;" : "=f"(f.x), "=f"(f.y) : "l"(a)); return f;
}
__device__ __forceinline__ ull f2fma(ull a, ull b, ull c) {
    ull d; asm("fma.rn.f32x2 %0, %1, %2, %3;" : "=l"(d) : "l"(a), "l"(b), "l"(c)); return d;
}
__device__ __forceinline__ ull f2mul(ull a, ull b) {
    ull d; asm("mul.rn.f32x2 %0, %1, %2;" : "=l"(d) : "l"(a), "l"(b)); return d;
}
__device__ __forceinline__ ull f2add(ull a, ull b) {
    ull d; asm("add.rn.f32x2 %0, %1, %2;" : "=l"(d) : "l"(a), "l"(b)); return d;
}

// load a 16-float column once, FMA into BOTH edges' 8 packed accumulators
__device__ __forceinline__ void colfma8_2(ull A[8], ull B[8],
                                          const ulonglong2* __restrict__ c,
                                          ull fa, ull fb) {
    ulonglong2 c0 = c[0], c1 = c[1], c2 = c[2], c3 = c[3];
    A[0] = f2fma(fa, c0.x, A[0]); B[0] = f2fma(fb, c0.x, B[0]);
    A[1] = f2fma(fa, c0.y, A[1]); B[1] = f2fma(fb, c0.y, B[1]);
    A[2] = f2fma(fa, c1.x, A[2]); B[2] = f2fma(fb, c1.x, B[2]);
    A[3] = f2fma(fa, c1.y, A[3]); B[3] = f2fma(fb, c1.y, B[3]);
    A[4] = f2fma(fa, c2.x, A[4]); B[4] = f2fma(fb, c2.x, B[4]);
    A[5] = f2fma(fa, c2.y, A[5]); B[5] = f2fma(fb, c2.y, B[5]);
    A[6] = f2fma(fa, c3.x, A[6]); B[6] = f2fma(fb, c3.x, B[6]);
    A[7] = f2fma(fa, c3.y, A[7]); B[7] = f2fma(fb, c3.y, B[7]);
}
__device__ __forceinline__ ull dot8p(const ull h[8], const ull T[8]) {
    ull s0 = f2mul(h[0], T[0]);
    ull s1 = f2mul(h[1], T[1]);
    s0 = f2fma(h[2], T[2], s0); s1 = f2fma(h[3], T[3], s1);
    s0 = f2fma(h[4], T[4], s0); s1 = f2fma(h[5], T[5], s1);
    s0 = f2fma(h[6], T[6], s0); s1 = f2fma(h[7], T[7], s1);
    return f2add(s0, s1);
}
// two coldots sharing one column load
__device__ __forceinline__ void coldot2(const ull hA[8], const ull hB[8],
                                        const ulonglong2* __restrict__ c,
                                        float& oA, float& oB) {
    ulonglong2 c0 = c[0], c1 = c[1], c2 = c[2], c3 = c[3];
    ull a0 = f2mul(hA[0], c0.x), a1 = f2mul(hA[1], c0.y);
    ull b0 = f2mul(hB[0], c0.x), b1 = f2mul(hB[1], c0.y);
    a0 = f2fma(hA[2], c1.x, a0); a1 = f2fma(hA[3], c1.y, a1);
    b0 = f2fma(hB[2], c1.x, b0); b1 = f2fma(hB[3], c1.y, b1);
    a0 = f2fma(hA[4], c2.x, a0); a1 = f2fma(hA[5], c2.y, a1);
    b0 = f2fma(hB[4], c2.x, b0); b1 = f2fma(hB[5], c2.y, b1);
    a0 = f2fma(hA[6], c3.x, a0); a1 = f2fma(hA[7], c3.y, a1);
    b0 = f2fma(hB[6], c3.x, b0); b1 = f2fma(hB[7], c3.y, b1);
    float2 ra = upk(f2add(a0, a1)); oA = ra.x + ra.y;
    float2 rb = upk(f2add(b0, b1)); oB = rb.x + rb.y;
}

__device__ __forceinline__ void ld16(float o[16], const float* __restrict__ p) {
    const float4* p4 = reinterpret_cast<const float4*>(p);
    float4 t0 = p4[0], t1 = p4[1], t2 = p4[2], t3 = p4[3];
    o[0] = t0.x; o[1] = t0.y; o[2] = t0.z; o[3] = t0.w;
    o[4] = t1.x; o[5] = t1.y; o[6] = t1.z; o[7] = t1.w;
    o[8] = t2.x; o[9] = t2.y; o[10] = t2.z; o[11] = t2.w;
    o[12] = t3.x; o[13] = t3.y; o[14] = t3.z; o[15] = t3.w;
}
__device__ __forceinline__ void ld24(float o[24], const float* __restrict__ p) {
    const float4* p4 = reinterpret_cast<const float4*>(p);
    #pragma unroll
    for (int k = 0; k < 6; ++k) {
        float4 t = p4[k];
        o[4 * k] = t.x; o[4 * k + 1] = t.y; o[4 * k + 2] = t.z; o[4 * k + 3] = t.w;
    }
}

// lerp 16-wide table row -> 8 packed regs
__device__ __forceinline__ void table_lerp(const float* __restrict__ tab, float d, ull h2[8]) {
    float uu = d * ((float)(TBL - 1) * 0.125f);
    int i0 = (int)uu;
    if (i0 < 0) i0 = 0;
    if (i0 > TBL - 2) i0 = TBL - 2;
    float f = uu - (float)i0;
    const float4* t0 = reinterpret_cast<const float4*>(tab + i0 * 16);
    #pragma unroll
    for (int k = 0; k < 4; ++k) {
        float4 A = t0[k], B = t0[k + 4];
        float h0 = fmaf(f, B.x - A.x, A.x);
        float h1 = fmaf(f, B.y - A.y, A.y);
        float h2v = fmaf(f, B.z - A.z, A.z);
        float h3 = fmaf(f, B.w - A.w, A.w);
        h2[2 * k] = pk(h0, h1);
        h2[2 * k + 1] = pk(h2v, h3);
    }
}

// -------- setup: weight transpose + radial MLP tables
__global__ void setup_kernel(const float* __restrict__ Wk2, const float* __restrict__ Wv2,
                             const float* __restrict__ Wk1, const float* __restrict__ Wv1) {
    int idx = blockIdx.x * 256 + threadIdx.x;
    if (idx < 9216) {
        g_WkT[idx] = Wk2[(idx & 15) * 576 + (idx >> 4)];
    } else if (idx < 18432) {
        int t = idx - 9216;
        g_WvT[t] = Wv2[(t & 15) * 576 + (t >> 4)];
    } else if (idx < 18432 + TBL) {
        int i = idx - 18432;
        float d = (float)i * (8.0f / (float)(TBL - 1));
        float emb[16];
        #pragma unroll
        for (int b = 0; b < 16; ++b) {
            float cb = 0.47058824f * (float)(b + 1);
            float diff = (d - cb) * 2.125f;
            float q = 1.0f - diff * diff;
            emb[b] = (q > 0.f) ? 33.7342930f * expf(-2.0f / q) : 0.f;
        }
        #pragma unroll
        for (int c = 0; c < 16; ++c) {
            float sk = 0.f, sv = 0.f;
            #pragma unroll
            for (int b = 0; b < 16; ++b) {
                sk = fmaf(emb[b], Wk1[b * 16 + c], sk);
                sv = fmaf(emb[b], Wv1[b * 16 + c], sv);
            }
            sk *= 0.25f; sv *= 0.25f;
            g_tk[i * 16 + c] = sk / (1.f + expf(-sk));
            g_tv[i * 16 + c] = sv / (1.f + expf(-sv));
        }
    }
}

// -------- per-node p0/p1 = x(WqWd) with norms folded; zero z and out
__global__ __launch_bounds__(128) void node_prep(
    const float* __restrict__ x,
    const float* __restrict__ Wq0, const float* __restrict__ Wq1,
    const float* __restrict__ Wd0, const float* __restrict__ Wd1,
    float* __restrict__ out, int n) {
    __shared__ float C0[256];
    __shared__ float C1[64];
    int t = threadIdx.x;
    for (int idx = t; idx < 256; idx += blockDim.x) {
        int u = idx >> 4, v = idx & 15;
        float s = 0.f;
        #pragma unroll
        for (int w = 0; w < 16; ++w) s = fmaf(Wq0[u * 16 + w], Wd0[w * 16 + v], s);
        C0[idx] = s * 0.25f;
    }
    if (t < 64) {
        int u = t >> 3, v = t & 7;
        float s = 0.f;
        #pragma unroll
        for (int w = 0; w < 8; ++w) s = fmaf(Wq1[u * 8 + w], Wd1[w * 8 + v], s);
        C1[t] = s * 0.2041241452f;  // 1/(sqrt(8)*sqrt(3))
    }
    __syncthreads();
    int i = blockIdx.x * blockDim.x + t;
    if (i >= n) return;

    float x0[16];
    #pragma unroll
    for (int u = 0; u < 16; ++u) x0[u] = x[i * 40 + u];
    #pragma unroll
    for (int v = 0; v < 16; ++v) {
        float s = 0.f;
        #pragma unroll
        for (int u = 0; u < 16; ++u) s = fmaf(x0[u], C0[u * 16 + v], s);
        g_p0[i * 16 + v] = s;
    }
    float x1[24];
    #pragma unroll
    for (int k = 0; k < 24; ++k) x1[k] = x[i * 40 + 16 + k];
    #pragma unroll
    for (int v = 0; v < 8; ++v) {
        #pragma unroll
        for (int c = 0; c < 3; ++c) {
            float s = 0.f;
            #pragma unroll
            for (int u = 0; u < 8; ++u) s = fmaf(x1[u * 3 + c], C1[u * 8 + v], s);
            g_p1[i * 24 + v * 3 + c] = s;
        }
    }
    g_z[i] = 0.f;
    float4 z4 = make_float4(0.f, 0.f, 0.f, 0.f);
    float4* o4 = reinterpret_cast<float4*>(out + i * 40);
    #pragma unroll
    for (int m = 0; m < 10; ++m) o4[m] = z4;
}

// -------- score kernel: TWO edges per thread, Wk column read once for both
__global__ __launch_bounds__(128, 4) void edge_score(
    const float* __restrict__ x, const int* __restrict__ ei,
    const float* __restrict__ ea, const float* __restrict__ amf, int E) {
    __shared__ __align__(16) float Wk[9216];
    {
        float4* s4 = reinterpret_cast<float4*>(Wk);
        const float4* g4 = reinterpret_cast<const float4*>(g_WkT);
        for (int i = threadIdx.x; i < 2304; i += 128) s4[i] = g4[i];
    }
    __syncthreads();
    const ulonglong2* WK = reinterpret_cast<const ulonglong2*>(Wk);

    int e0 = blockIdx.x * 256 + threadIdx.x;
    int e1 = e0 + 128;
    bool v0 = e0 < E, v1 = e1 < E;
    int ia = v0 ? e0 : 0, ib = v1 ? e1 : 0;
    int srcA = ei[ia], dstA = ei[E + ia];
    int srcB = ei[ib], dstB = ei[E + ib];
    const float4 shA = reinterpret_cast<const float4*>(ea)[ia];
    const float4 shB = reinterpret_cast<const float4*>(ea)[ib];
    float dA = amf[ia], dB = amf[ib];

    float x0A[16], x0B[16], p0A[16], p0B[16];
    ld16(x0A, x + srcA * 40); ld16(x0B, x + srcB * 40);
    ld16(p0A, g_p0 + dstA * 16); ld16(p0B, g_p0 + dstB * 16);

    ull mA[8], mB[8];
    #pragma unroll
    for (int i = 0; i < 8; ++i) { mA[i] = pk2(0.f); mB[i] = pk2(0.f); }

    // block1: j=u*16+w, g = (x0[u]*sh0)*p0[w]
    #pragma unroll 1
    for (int u = 0; u < 16; ++u) {
        float aA = x0A[u] * shA.x, aB = x0B[u] * shB.x;
        #pragma unroll 4
        for (int w = 0; w < 16; ++w)
            colfma8_2(mA, mB, WK + (u * 16 + w) * 4, pk2(aA * p0A[w]), pk2(aB * p0B[w]));
    }
    // r from p1 (streamed, discarded)
    float rA[8], rB[8];
    {
        float tA[24], tB[24];
        ld24(tA, g_p1 + dstA * 24); ld24(tB, g_p1 + dstB * 24);
        #pragma unroll
        for (int w = 0; w < 8; ++w) {
            rA[w] = tA[3 * w] * shA.y + tA[3 * w + 1] * shA.z + tA[3 * w + 2] * shA.w;
            rB[w] = tB[3 * w] * shB.y + tB[3 * w + 1] * shB.z + tB[3 * w + 2] * shB.w;
        }
    }
    // block2: j=256+u*8+w, g = x0[u]*r[w]
    #pragma unroll 1
    for (int u = 0; u < 16; ++u) {
        float xA = x0A[u], xB = x0B[u];
        #pragma unroll 4
        for (int w = 0; w < 8; ++w)
            colfma8_2(mA, mB, WK + (256 + u * 8 + w) * 4, pk2(xA * rA[w]), pk2(xB * rB[w]));
    }
    // dd (x1 streamed, discarded)
    float ddA[8], ddB[8];
    {
        float tA[24], tB[24];
        ld24(tA, x + srcA * 40 + 16); ld24(tB, x + srcB * 40 + 16);
        #pragma unroll
        for (int u = 0; u < 8; ++u) {
            ddA[u] = (tA[3 * u] * shA.y + tA[3 * u + 1] * shA.z + tA[3 * u + 2] * shA.w) * 0.57735027f;
            ddB[u] = (tB[3 * u] * shB.y + tB[3 * u + 1] * shB.z + tB[3 * u + 2] * shB.w) * 0.57735027f;
        }
    }
    // block4: j=448+u*16+w, g = dd[u]*p0[w]
    #pragma unroll 1
    for (int u = 0; u < 8; ++u) {
        float aA = ddA[u], aB = ddB[u];
        #pragma unroll 4
        for (int w = 0; w < 16; ++w)
            colfma8_2(mA, mB, WK + (448 + u * 16 + w) * 4, pk2(aA * p0A[w]), pk2(aB * p0B[w]));
    }
    // block3: j=384+u*8+w, g = (x1*sh0)·p1[w]; x1 resident, p1 streamed per w
    float x1A[24], x1B[24];
    ld24(x1A, x + srcA * 40 + 16); ld24(x1B, x + srcB * 40 + 16);
    #pragma unroll
    for (int k = 0; k < 24; ++k) { x1A[k] *= shA.x; x1B[k] *= shB.x; }
    {
        const float* pA = g_p1 + dstA * 24;
        const float* pB = g_p1 + dstB * 24;
        #pragma unroll 1
        for (int w = 0; w < 8; ++w) {
            float qA0 = pA[3 * w], qA1 = pA[3 * w + 1], qA2 = pA[3 * w + 2];
            float qB0 = pB[3 * w], qB1 = pB[3 * w + 1], qB2 = pB[3 * w + 2];
            #pragma unroll 4
            for (int u = 0; u < 8; ++u) {
                float gA = x1A[3 * u] * qA0 + x1A[3 * u + 1] * qA1 + x1A[3 * u + 2] * qA2;
                float gB = x1B[3 * u] * qB0 + x1B[3 * u + 1] * qB1 + x1B[3 * u + 2] * qB2;
                colfma8_2(mA, mB, WK + (384 + u * 8 + w) * 4, pk2(gA), pk2(gB));
            }
        }
    }
    // finalize (reuse one hk buffer for both edges)
    ull hk[8];
    table_lerp(g_tk, dA, hk);
    float2 sA2 = upk(dot8p(hk, mA));
    table_lerp(g_tk, dB, hk);
    float2 sB2 = upk(dot8p(hk, mB));
    float scoreA = (sA2.x + sA2.y) * 0.0028527222f;
    float scoreB = (sB2.x + sB2.y) * 0.0028527222f;
    float tcA = 10.0f * (1.0f - dA * 0.125f);
    float tcB = 10.0f * (1.0f - dB * 0.125f);
    float cutA = (tcA > 0.f) ? __expf(-__frcp_rn(tcA)) : 0.f;
    float cutB = (tcB > 0.f) ? __expf(-__frcp_rn(tcB)) : 0.f;
    float evA = cutA * __expf(scoreA);
    float evB = cutB * __expf(scoreB);
    if (v0) { g_expv[e0] = evA; atomicAdd(&g_z[dstA], evA); }
    if (v1) { g_expv[e1] = evB; atomicAdd(&g_z[dstB], evB); }
}

// -------- value kernel: TWO edges per thread
__global__ __launch_bounds__(128, 4) void edge_value(
    const float* __restrict__ x, const int* __restrict__ ei,
    const float* __restrict__ ea, const float* __restrict__ amf,
    float* __restrict__ out, int E) {
    __shared__ __align__(16) float Wv[9216];
    {
        float4* s4 = reinterpret_cast<float4*>(Wv);
        const float4* g4 = reinterpret_cast<const float4*>(g_WvT);
        for (int i = threadIdx.x; i < 2304; i += 128) s4[i] = g4[i];
    }
    __syncthreads();
    const ulonglong2* WV = reinterpret_cast<const ulonglong2*>(Wv);

    int e0 = blockIdx.x * 256 + threadIdx.x;
    int e1 = e0 + 128;
    bool v0 = e0 < E, v1 = e1 < E;
    int ia = v0 ? e0 : 0, ib = v1 ? e1 : 0;
    int srcA = ei[ia], dstA = ei[E + ia];
    int srcB = ei[ib], dstB = ei[E + ib];
    const float4 shA = reinterpret_cast<const float4*>(ea)[ia];
    const float4 shB = reinterpret_cast<const float4*>(ea)[ib];
    float dA = amf[ia], dB = amf[ib];

    float fsA = sqrtf(g_expv[ia]) * 0.0510310363f;
    float fsB = sqrtf(g_expv[ib]) * 0.0510310363f;

    ull hvA[8], hvB[8];
    table_lerp(g_tv, dA, hvA);
    table_lerp(g_tv, dB, hvB);

    float x0A[16], x0B[16];
    ld16(x0A, x + srcA * 40); ld16(x0B, x + srcB * 40);

    // A-phase: A[w] = hv . (sum_u x0[u] W2col(u,w)), cols 256+u*8+w
    float AA[8], AB[8];
    #pragma unroll 1
    for (int w = 0; w < 8; ++w) {
        ull UA[8], UB[8];
        #pragma unroll
        for (int i = 0; i < 8; ++i) { UA[i] = pk2(0.f); UB[i] = pk2(0.f); }
        #pragma unroll 4
        for (int u = 0; u < 16; ++u)
            colfma8_2(UA, UB, WV + (256 + u * 8 + w) * 4, pk2(x0A[u]), pk2(x0B[u]));
        float2 tA = upk(dot8p(hvA, UA)); AA[w] = tA.x + tA.y;
        float2 tB = upk(dot8p(hvB, UB)); AB[w] = tB.x + tB.y;
    }
    // dd (x1 streamed)
    float ddA[8], ddB[8];
    {
        float tA[24], tB[24];
        ld24(tA, x + srcA * 40 + 16); ld24(tB, x + srcB * 40 + 16);
        #pragma unroll
        for (int u = 0; u < 8; ++u) {
            ddA[u] = (tA[3 * u] * shA.y + tA[3 * u + 1] * shA.z + tA[3 * u + 2] * shA.w) * 0.57735027f;
            ddB[u] = (tB[3 * u] * shB.y + tB[3 * u + 1] * shB.z + tB[3 * u + 2] * shB.w) * 0.57735027f;
        }
    }
    float* obA = out + dstA * 40;
    float* obB = out + dstB * 40;

    // o0: scale x0 in place to a0 = x0*sh0; per w: U over block1(16,a0) + block4(8,dd)
    #pragma unroll
    for (int u = 0; u < 16; ++u) { x0A[u] *= shA.x; x0B[u] *= shB.x; }
    #pragma unroll 1
    for (int w = 0; w < 16; ++w) {
        ull UA[8], UB[8];
        #pragma unroll
        for (int i = 0; i < 8; ++i) { UA[i] = pk2(0.f); UB[i] = pk2(0.f); }
        #pragma unroll 4
        for (int u = 0; u < 16; ++u)
            colfma8_2(UA, UB, WV + (u * 16 + w) * 4, pk2(x0A[u]), pk2(x0B[u]));
        #pragma unroll 4
        for (int u = 0; u < 8; ++u)
            colfma8_2(UA, UB, WV + (448 + u * 16 + w) * 4, pk2(ddA[u]), pk2(ddB[u]));
        float2 sA = upk(dot8p(hvA, UA));
        float2 sB = upk(dot8p(hvB, UB));
        if (v0) atomicAdd(obA + w, (sA.x + sA.y) * fsA);
        if (v1) atomicAdd(obB + w, (sB.x + sB.y) * fsB);
    }
    // o1: x1s resident; per w: vxyz = A[w]*sh1 + sum_u (hv.W3col)*x1s[u,:]
    float x1A[24], x1B[24];
    ld24(x1A, x + srcA * 40 + 16); ld24(x1B, x + srcB * 40 + 16);
    #pragma unroll
    for (int k = 0; k < 24; ++k) { x1A[k] *= shA.x; x1B[k] *= shB.x; }
    #pragma unroll 1
    for (int w = 0; w < 8; ++w) {
        float vxA = AA[w] * shA.y, vyA = AA[w] * shA.z, vzA = AA[w] * shA.w;
        float vxB = AB[w] * shB.y, vyB = AB[w] * shB.z, vzB = AB[w] * shB.w;
        #pragma unroll 4
        for (int u = 0; u < 8; ++u) {
            float sA_, sB_;
            coldot2(hvA, hvB, WV + (384 + u * 8 + w) * 4, sA_, sB_);
            vxA = fmaf(sA_, x1A[3 * u], vxA);
            vyA = fmaf(sA_, x1A[3 * u + 1], vyA);
            vzA = fmaf(sA_, x1A[3 * u + 2], vzA);
            vxB = fmaf(sB_, x1B[3 * u], vxB);
            vyB = fmaf(sB_, x1B[3 * u + 1], vyB);
            vzB = fmaf(sB_, x1B[3 * u + 2], vzB);
        }
        if (v0) {
            atomicAdd(obA + 16 + 3 * w, vxA * fsA);
            atomicAdd(obA + 17 + 3 * w, vyA * fsA);
            atomicAdd(obA + 18 + 3 * w, vzA * fsA);
        }
        if (v1) {
            atomicAdd(obB + 16 + 3 * w, vxB * fsB);
            atomicAdd(obB + 17 + 3 * w, vyB * fsB);
            atomicAdd(obB + 18 + 3 * w, vzB * fsB);
        }
    }
}

// -------- epilogue: out[i] *= rsqrt(z[i])
__global__ void normalize(float* __restrict__ out, int n) {
    int i = blockIdx.x * 128 + threadIdx.x;
    if (i >= n) return;
    float zz = g_z[i];
    if (zz <= 0.f) zz = 1.f;
    float s = rsqrtf(zz);
    float4* o4 = reinterpret_cast<float4*>(out + i * 40);
    #pragma unroll
    for (int m = 0; m < 10; ++m) {
        float4 v = o4[m];
        v.x *= s; v.y *= s; v.z *= s; v.w *= s;
        o4[m] = v;
    }
}

extern "C" void kernel_launch(void* const* d_in, const int* in_sizes, int n_in,
                              void* d_out, int out_size) {
    const float* x   = (const float*)d_in[0];
    const int*   ei  = (const int*)d_in[1];
    const float* ea  = (const float*)d_in[2];
    const float* amf = (const float*)d_in[5];
    const float* Wq0 = (const float*)d_in[6];
    const float* Wq1 = (const float*)d_in[7];
    const float* Wk1 = (const float*)d_in[8];
    const float* Wk2 = (const float*)d_in[9];
    const float* Wv1 = (const float*)d_in[10];
    const float* Wv2 = (const float*)d_in[11];
    const float* Wd0 = (const float*)d_in[12];
    const float* Wd1 = (const float*)d_in[13];
    float* out = (float*)d_out;

    int n = in_sizes[0] / 40;
    int E = in_sizes[2] / 4;

    setup_kernel<<<(18432 + TBL + 255) / 256, 256>>>(Wk2, Wv2, Wk1, Wv1);
    node_prep<<<(n + 127) / 128, 128>>>(x, Wq0, Wq1, Wd0, Wd1, out, n);
    int grid = (E + 255) / 256;
    edge_score<<<grid, 128>>>(x, ei, ea, amf, E);
    edge_value<<<grid, 128>>>(x, ei, ea, amf, out, E);
    normalize<<<(n + 127) / 128, 128>>>(out, n);
}

// round 11
// speedup vs baseline: 1.5758x; 1.5758x over previous
#include <cuda_runtime.h>
#include <math.h>

#define NMAX 10000
#define EMAX 160000
#define TBLM 4096
typedef unsigned long long ull;

// device scratch (no runtime allocation)
__device__ __align__(16) float g_p0[NMAX * 16];
__device__ __align__(16) float g_p1[NMAX * 24];
__device__ float g_z[NMAX];
__device__ float g_expv[EMAX];
__device__ __align__(16) float g_hk[(TBLM + 1) * 16];
__device__ __align__(16) float g_hv[(TBLM + 1) * 16];
__device__ __align__(16) float g_Mk[(TBLM + 1) * 576];  // M(d)[j] = hk(d) . Wk2col_j
__device__ __align__(16) float g_Mv[(TBLM + 1) * 576];
// edge sort (by d-bin) scratch
__device__ int g_cnt[TBLM];
__device__ int g_off[TBLM];
__device__ int g_src[EMAX];
__device__ int g_dst[EMAX];
__device__ __align__(16) float4 g_sea[EMAX];
__device__ float g_sd[EMAX];

// ---------- packed f32x2 primitives ----------
__device__ __forceinline__ ull pk2(float a) {
    ull r; asm("mov.b64 %0, {%1,%1};" : "=l"(r) : "f"(a)); return r;
}
__device__ __forceinline__ ull pk(float a, float b) {
    ull r; asm("mov.b64 %0, {%1,%2};" : "=l"(r) : "f"(a), "f"(b)); return r;
}
__device__ __forceinline__ float2 upk(ull a) {
    float2 f; asm("mov.b64 {%0,%1}, %2;" : "=f"(f.x), "=f"(f.y) : "l"(a)); return f;
}
__device__ __forceinline__ ull f2fma(ull a, ull b, ull c) {
    ull d; asm("fma.rn.f32x2 %0, %1, %2, %3;" : "=l"(d) : "l"(a), "l"(b), "l"(c)); return d;
}
__device__ __forceinline__ ull f2mul(ull a, ull b) {
    ull d; asm("mul.rn.f32x2 %0, %1, %2;" : "=l"(d) : "l"(a), "l"(b)); return d;
}
__device__ __forceinline__ ull f2add(ull a, ull b) {
    ull d; asm("add.rn.f32x2 %0, %1, %2;" : "=l"(d) : "l"(a), "l"(b)); return d;
}

__device__ __forceinline__ void ld16(float o[16], const float* __restrict__ p) {
    const float4* p4 = reinterpret_cast<const float4*>(p);
    float4 t0 = p4[0], t1 = p4[1], t2 = p4[2], t3 = p4[3];
    o[0] = t0.x; o[1] = t0.y; o[2] = t0.z; o[3] = t0.w;
    o[4] = t1.x; o[5] = t1.y; o[6] = t1.z; o[7] = t1.w;
    o[8] = t2.x; o[9] = t2.y; o[10] = t2.z; o[11] = t2.w;
    o[12] = t3.x; o[13] = t3.y; o[14] = t3.z; o[15] = t3.w;
}
__device__ __forceinline__ void ld24(float o[24], const float* __restrict__ p) {
    const float4* p4 = reinterpret_cast<const float4*>(p);
    #pragma unroll
    for (int k = 0; k < 6; ++k) {
        float4 t = p4[k];
        o[4 * k] = t.x; o[4 * k + 1] = t.y; o[4 * k + 2] = t.z; o[4 * k + 3] = t.w;
    }
}

// -------- setup: radial h rows + zero hist
__global__ void build_h(const float* __restrict__ Wk1, const float* __restrict__ Wv1) {
    int i = blockIdx.x * 256 + threadIdx.x;
    if (i < TBLM) g_cnt[i] = 0;
    if (i > TBLM) return;
    float d = (float)i * (8.0f / (float)TBLM);
    float emb[16];
    #pragma unroll
    for (int b = 0; b < 16; ++b) {
        float cb = 0.47058824f * (float)(b + 1);
        float diff = (d - cb) * 2.125f;
        float q = 1.0f - diff * diff;
        emb[b] = (q > 0.f) ? 33.7342930f * expf(-2.0f / q) : 0.f;
    }
    #pragma unroll
    for (int c = 0; c < 16; ++c) {
        float sk = 0.f, sv = 0.f;
        #pragma unroll
        for (int b = 0; b < 16; ++b) {
            sk = fmaf(emb[b], Wk1[b * 16 + c], sk);
            sv = fmaf(emb[b], Wv1[b * 16 + c], sv);
        }
        sk *= 0.25f; sv *= 0.25f;
        g_hk[i * 16 + c] = sk / (1.f + expf(-sk));
        g_hv[i * 16 + c] = sv / (1.f + expf(-sv));
    }
}

// -------- build M tables: M[row][j] = h(row) . W[:, j]; thread does 4 consecutive j
__global__ void build_M(const float* __restrict__ Wk2, const float* __restrict__ Wv2) {
    int idx = blockIdx.x * 256 + threadIdx.x;
    int row = idx / 288;
    if (row > TBLM) return;
    int rem = idx % 288;
    int tbl = rem / 144;
    int j4 = (rem % 144) * 4;
    const float* h = (tbl ? g_hv : g_hk) + row * 16;
    const float* W = tbl ? Wv2 : Wk2;
    float a0 = 0.f, a1 = 0.f, a2 = 0.f, a3 = 0.f;
    #pragma unroll
    for (int c = 0; c < 16; ++c) {
        float hc = h[c];
        const float4 w = *reinterpret_cast<const float4*>(W + c * 576 + j4);
        a0 = fmaf(hc, w.x, a0); a1 = fmaf(hc, w.y, a1);
        a2 = fmaf(hc, w.z, a2); a3 = fmaf(hc, w.w, a3);
    }
    float* dst = (tbl ? g_Mv : g_Mk) + row * 576 + j4;
    *reinterpret_cast<float4*>(dst) = make_float4(a0, a1, a2, a3);
}

// -------- counting sort by d-bin
__global__ void hist_kernel(const float* __restrict__ amf, int E) {
    int e = blockIdx.x * 256 + threadIdx.x;
    if (e >= E) return;
    int b = (int)(amf[e] * ((float)TBLM * 0.125f));
    if (b < 0) b = 0;
    if (b > TBLM - 1) b = TBLM - 1;
    atomicAdd(&g_cnt[b], 1);
}
__global__ __launch_bounds__(1024) void scan_kernel(int n) {
    __shared__ int part[1024];
    int t = threadIdx.x;
    int chunk = (n + 1023) / 1024;
    int base = t * chunk;
    int s = 0;
    for (int i = 0; i < chunk; ++i) {
        int j = base + i;
        if (j < n) s += g_cnt[j];
    }
    part[t] = s;
    __syncthreads();
    for (int off = 1; off < 1024; off <<= 1) {
        int v = (t >= off) ? part[t - off] : 0;
        __syncthreads();
        part[t] += v;
        __syncthreads();
    }
    int run = (t > 0) ? part[t - 1] : 0;
    for (int i = 0; i < chunk; ++i) {
        int j = base + i;
        if (j < n) {
            int c = g_cnt[j];
            g_off[j] = run;
            run += c;
        }
    }
}
__global__ void scatter_kernel(const int* __restrict__ ei, const float* __restrict__ ea,
                               const float* __restrict__ amf, int E) {
    int e = blockIdx.x * 256 + threadIdx.x;
    if (e >= E) return;
    float d = amf[e];
    int b = (int)(d * ((float)TBLM * 0.125f));
    if (b < 0) b = 0;
    if (b > TBLM - 1) b = TBLM - 1;
    int pos = atomicAdd(&g_off[b], 1);
    g_src[pos] = ei[e];
    g_dst[pos] = ei[E + e];
    g_sea[pos] = reinterpret_cast<const float4*>(ea)[e];
    g_sd[pos] = d;
}

// -------- per-node p0/p1 = x(WqWd) with norms folded; zero z and out
__global__ __launch_bounds__(128) void node_prep(
    const float* __restrict__ x,
    const float* __restrict__ Wq0, const float* __restrict__ Wq1,
    const float* __restrict__ Wd0, const float* __restrict__ Wd1,
    float* __restrict__ out, int n) {
    __shared__ float C0[256];
    __shared__ float C1[64];
    int t = threadIdx.x;
    for (int idx = t; idx < 256; idx += blockDim.x) {
        int u = idx >> 4, v = idx & 15;
        float s = 0.f;
        #pragma unroll
        for (int w = 0; w < 16; ++w) s = fmaf(Wq0[u * 16 + w], Wd0[w * 16 + v], s);
        C0[idx] = s * 0.25f;
    }
    if (t < 64) {
        int u = t >> 3, v = t & 7;
        float s = 0.f;
        #pragma unroll
        for (int w = 0; w < 8; ++w) s = fmaf(Wq1[u * 8 + w], Wd1[w * 8 + v], s);
        C1[t] = s * 0.2041241452f;  // 1/(sqrt(8)*sqrt(3))
    }
    __syncthreads();
    int i = blockIdx.x * blockDim.x + t;
    if (i >= n) return;

    float x0[16];
    #pragma unroll
    for (int u = 0; u < 16; ++u) x0[u] = x[i * 40 + u];
    #pragma unroll
    for (int v = 0; v < 16; ++v) {
        float s = 0.f;
        #pragma unroll
        for (int u = 0; u < 16; ++u) s = fmaf(x0[u], C0[u * 16 + v], s);
        g_p0[i * 16 + v] = s;
    }
    float x1[24];
    #pragma unroll
    for (int k = 0; k < 24; ++k) x1[k] = x[i * 40 + 16 + k];
    #pragma unroll
    for (int v = 0; v < 8; ++v) {
        #pragma unroll
        for (int c = 0; c < 3; ++c) {
            float s = 0.f;
            #pragma unroll
            for (int u = 0; u < 8; ++u) s = fmaf(x1[u * 3 + c], C1[u * 8 + v], s);
            g_p1[i * 24 + v * 3 + c] = s;
        }
    }
    g_z[i] = 0.f;
    float4 z4 = make_float4(0.f, 0.f, 0.f, 0.f);
    float4* o4 = reinterpret_cast<float4*>(out + i * 40);
    #pragma unroll
    for (int m = 0; m < 10; ++m) o4[m] = z4;
}

// -------- score pass over one M row
__device__ __forceinline__ float score_pass(
    const float* __restrict__ M, const float x0[16], const ull p0p[8],
    const ull rp[4], const float dd[8], const float x1s[24],
    const float p1[24], float sh0) {
    const ulonglong2* M2 = reinterpret_cast<const ulonglong2*>(M);
    ull acc = pk2(0.f);
    // B1: j=u*16+w, score += (x0u*sh0) * (p0 . Mrow_u)
    #pragma unroll
    for (int u = 0; u < 16; ++u) {
        ulonglong2 c0 = M2[u * 4], c1 = M2[u * 4 + 1], c2 = M2[u * 4 + 2], c3 = M2[u * 4 + 3];
        ull t = f2mul(p0p[0], c0.x);
        t = f2fma(p0p[1], c0.y, t); t = f2fma(p0p[2], c1.x, t); t = f2fma(p0p[3], c1.y, t);
        t = f2fma(p0p[4], c2.x, t); t = f2fma(p0p[5], c2.y, t);
        t = f2fma(p0p[6], c3.x, t); t = f2fma(p0p[7], c3.y, t);
        acc = f2fma(pk2(x0[u] * sh0), t, acc);
    }
    // B2: j=256+u*8+w, score += x0u * (r . Mrow_u)
    #pragma unroll
    for (int u = 0; u < 16; ++u) {
        ulonglong2 c0 = M2[64 + u * 2], c1 = M2[64 + u * 2 + 1];
        ull t = f2mul(rp[0], c0.x);
        t = f2fma(rp[1], c0.y, t); t = f2fma(rp[2], c1.x, t); t = f2fma(rp[3], c1.y, t);
        acc = f2fma(pk2(x0[u]), t, acc);
    }
    // B4: j=448+u*16+w, score += dd_u * (p0 . Mrow_u)
    #pragma unroll
    for (int u = 0; u < 8; ++u) {
        ulonglong2 c0 = M2[112 + u * 4], c1 = M2[112 + u * 4 + 1],
                   c2 = M2[112 + u * 4 + 2], c3 = M2[112 + u * 4 + 3];
        ull t = f2mul(p0p[0], c0.x);
        t = f2fma(p0p[1], c0.y, t); t = f2fma(p0p[2], c1.x, t); t = f2fma(p0p[3], c1.y, t);
        t = f2fma(p0p[4], c2.x, t); t = f2fma(p0p[5], c2.y, t);
        t = f2fma(p0p[6], c3.x, t); t = f2fma(p0p[7], c3.y, t);
        acc = f2fma(pk2(dd[u]), t, acc);
    }
    // B3: j=384+u*8+w, score += sum_u x1s_u . (sum_w M3[u][w] p1_w)
    float s3 = 0.f;
    #pragma unroll
    for (int u = 0; u < 8; ++u) {
        const float4* m4 = reinterpret_cast<const float4*>(M + 384 + u * 8);
        float4 A = m4[0], B = m4[1];
        float tvx = A.x * p1[0] + A.y * p1[3] + A.z * p1[6] + A.w * p1[9]
                  + B.x * p1[12] + B.y * p1[15] + B.z * p1[18] + B.w * p1[21];
        float tvy = A.x * p1[1] + A.y * p1[4] + A.z * p1[7] + A.w * p1[10]
                  + B.x * p1[13] + B.y * p1[16] + B.z * p1[19] + B.w * p1[22];
        float tvz = A.x * p1[2] + A.y * p1[5] + A.z * p1[8] + A.w * p1[11]
                  + B.x * p1[14] + B.y * p1[17] + B.z * p1[20] + B.w * p1[23];
        s3 += x1s[3 * u] * tvx + x1s[3 * u + 1] * tvy + x1s[3 * u + 2] * tvz;
    }
    float2 a2 = upk(acc);
    return a2.x + a2.y + s3;
}

// -------- score kernel: one edge/thread (d-sorted), M-table contraction
__global__ __launch_bounds__(128) void edge_score(const float* __restrict__ x, int E) {
    int e = blockIdx.x * 128 + threadIdx.x;
    if (e >= E) return;
    int src = g_src[e], dst = g_dst[e];
    float4 sh = g_sea[e];
    float d = g_sd[e];

    float x0[16]; ld16(x0, x + src * 40);
    ull p0p[8];
    {
        float p0[16]; ld16(p0, g_p0 + dst * 16);
        #pragma unroll
        for (int k = 0; k < 8; ++k) p0p[k] = pk(p0[2 * k], p0[2 * k + 1]);
    }
    float p1[24]; ld24(p1, g_p1 + dst * 24);
    ull rp[4];
    #pragma unroll
    for (int k = 0; k < 4; ++k) {
        float r0 = p1[6 * k] * sh.y + p1[6 * k + 1] * sh.z + p1[6 * k + 2] * sh.w;
        float r1 = p1[6 * k + 3] * sh.y + p1[6 * k + 4] * sh.z + p1[6 * k + 5] * sh.w;
        rp[k] = pk(r0, r1);
    }
    float x1s[24], dd[8];
    {
        float t[24]; ld24(t, x + src * 40 + 16);
        #pragma unroll
        for (int u = 0; u < 8; ++u) {
            dd[u] = (t[3 * u] * sh.y + t[3 * u + 1] * sh.z + t[3 * u + 2] * sh.w) * 0.57735027f;
            x1s[3 * u] = t[3 * u] * sh.x;
            x1s[3 * u + 1] = t[3 * u + 1] * sh.x;
            x1s[3 * u + 2] = t[3 * u + 2] * sh.x;
        }
    }
    float uu = d * ((float)TBLM * 0.125f);
    int i0 = (int)uu;
    if (i0 < 0) i0 = 0;
    if (i0 > TBLM - 1) i0 = TBLM - 1;
    float f = uu - (float)i0;

    float s0 = score_pass(g_Mk + i0 * 576, x0, p0p, rp, dd, x1s, p1, sh.x);
    float s1 = score_pass(g_Mk + (i0 + 1) * 576, x0, p0p, rp, dd, x1s, p1, sh.x);
    float score = (s0 + f * (s1 - s0)) * 0.0028527222f;  // 1/(4*sqrt(24)*sqrt(320))
    float tc = 10.0f * (1.0f - d * 0.125f);
    float cut = (tc > 0.f) ? __expf(-__frcp_rn(tc)) : 0.f;
    float ev = cut * __expf(score);
    g_expv[e] = ev;
    atomicAdd(&g_z[dst], ev);
}

// -------- value pass over one M row: accumulate o0 (packed) and o1 (scalar)
__device__ __forceinline__ void value_pass(
    const float* __restrict__ M, const float x0[16], const float dd[8],
    const float x1s[24], float4 sh, ull o0p[8], float o1[24]) {
    const ulonglong2* M2 = reinterpret_cast<const ulonglong2*>(M);
    // B1: o0[w] += (x0u*sh0) * M1[u][w]
    #pragma unroll
    for (int u = 0; u < 16; ++u) {
        ull fa = pk2(x0[u] * sh.x);
        ulonglong2 c0 = M2[u * 4], c1 = M2[u * 4 + 1], c2 = M2[u * 4 + 2], c3 = M2[u * 4 + 3];
        o0p[0] = f2fma(fa, c0.x, o0p[0]); o0p[1] = f2fma(fa, c0.y, o0p[1]);
        o0p[2] = f2fma(fa, c1.x, o0p[2]); o0p[3] = f2fma(fa, c1.y, o0p[3]);
        o0p[4] = f2fma(fa, c2.x, o0p[4]); o0p[5] = f2fma(fa, c2.y, o0p[5]);
        o0p[6] = f2fma(fa, c3.x, o0p[6]); o0p[7] = f2fma(fa, c3.y, o0p[7]);
    }
    // B4: o0[w] += dd_u * M4[u][w]
    #pragma unroll
    for (int u = 0; u < 8; ++u) {
        ull fa = pk2(dd[u]);
        ulonglong2 c0 = M2[112 + u * 4], c1 = M2[112 + u * 4 + 1],
                   c2 = M2[112 + u * 4 + 2], c3 = M2[112 + u * 4 + 3];
        o0p[0] = f2fma(fa, c0.x, o0p[0]); o0p[1] = f2fma(fa, c0.y, o0p[1]);
        o0p[2] = f2fma(fa, c1.x, o0p[2]); o0p[3] = f2fma(fa, c1.y, o0p[3]);
        o0p[4] = f2fma(fa, c2.x, o0p[4]); o0p[5] = f2fma(fa, c2.y, o0p[5]);
        o0p[6] = f2fma(fa, c3.x, o0p[6]); o0p[7] = f2fma(fa, c3.y, o0p[7]);
    }
    // B2: A[w] = sum_u x0u M2[u][w]
    ull Ap[4] = {pk2(0.f), pk2(0.f), pk2(0.f), pk2(0.f)};
    #pragma unroll
    for (int u = 0; u < 16; ++u) {
        ull fa = pk2(x0[u]);
        ulonglong2 c0 = M2[64 + u * 2], c1 = M2[64 + u * 2 + 1];
        Ap[0] = f2fma(fa, c0.x, Ap[0]); Ap[1] = f2fma(fa, c0.y, Ap[1]);
        Ap[2] = f2fma(fa, c1.x, Ap[2]); Ap[3] = f2fma(fa, c1.y, Ap[3]);
    }
    // B3: o1[w,:] += M3[u][w] * x1s[u,:]
    #pragma unroll
    for (int u = 0; u < 8; ++u) {
        const float4* m4 = reinterpret_cast<const float4*>(M + 384 + u * 8);
        float4 A = m4[0], B = m4[1];
        float xa = x1s[3 * u], xb = x1s[3 * u + 1], xc = x1s[3 * u + 2];
        o1[0] = fmaf(A.x, xa, o1[0]);  o1[1] = fmaf(A.x, xb, o1[1]);  o1[2] = fmaf(A.x, xc, o1[2]);
        o1[3] = fmaf(A.y, xa, o1[3]);  o1[4] = fmaf(A.y, xb, o1[4]);  o1[5] = fmaf(A.y, xc, o1[5]);
        o1[6] = fmaf(A.z, xa, o1[6]);  o1[7] = fmaf(A.z, xb, o1[7]);  o1[8] = fmaf(A.z, xc, o1[8]);
        o1[9] = fmaf(A.w, xa, o1[9]);  o1[10] = fmaf(A.w, xb, o1[10]); o1[11] = fmaf(A.w, xc, o1[11]);
        o1[12] = fmaf(B.x, xa, o1[12]); o1[13] = fmaf(B.x, xb, o1[13]); o1[14] = fmaf(B.x, xc, o1[14]);
        o1[15] = fmaf(B.y, xa, o1[15]); o1[16] = fmaf(B.y, xb, o1[16]); o1[17] = fmaf(B.y, xc, o1[17]);
        o1[18] = fmaf(B.z, xa, o1[18]); o1[19] = fmaf(B.z, xb, o1[19]); o1[20] = fmaf(B.z, xc, o1[20]);
        o1[21] = fmaf(B.w, xa, o1[21]); o1[22] = fmaf(B.w, xb, o1[22]); o1[23] = fmaf(B.w, xc, o1[23]);
    }
    // A-term: o1[w,:] += A[w] * sh1
    #pragma unroll
    for (int k = 0; k < 4; ++k) {
        float2 a2 = upk(Ap[k]);
        int w0 = 2 * k, w1 = 2 * k + 1;
        o1[3 * w0] = fmaf(a2.x, sh.y, o1[3 * w0]);
        o1[3 * w0 + 1] = fmaf(a2.x, sh.z, o1[3 * w0 + 1]);
        o1[3 * w0 + 2] = fmaf(a2.x, sh.w, o1[3 * w0 + 2]);
        o1[3 * w1] = fmaf(a2.y, sh.y, o1[3 * w1]);
        o1[3 * w1 + 1] = fmaf(a2.y, sh.z, o1[3 * w1 + 1]);
        o1[3 * w1 + 2] = fmaf(a2.y, sh.w, o1[3 * w1 + 2]);
    }
}

// -------- value kernel: one edge/thread (d-sorted), M-table contraction
__global__ __launch_bounds__(128) void edge_value(
    const float* __restrict__ x, float* __restrict__ out, int E) {
    int e = blockIdx.x * 128 + threadIdx.x;
    if (e >= E) return;
    int src = g_src[e], dst = g_dst[e];
    float4 sh = g_sea[e];
    float d = g_sd[e];
    float fs = sqrtf(g_expv[e]) * 0.0510310363f;  // sqrt(ev)/(4*sqrt(24))

    float x0[16]; ld16(x0, x + src * 40);
    float x1s[24], dd[8];
    {
        float t[24]; ld24(t, x + src * 40 + 16);
        #pragma unroll
        for (int u = 0; u < 8; ++u) {
            dd[u] = (t[3 * u] * sh.y + t[3 * u + 1] * sh.z + t[3 * u + 2] * sh.w) * 0.57735027f;
            x1s[3 * u] = t[3 * u] * sh.x;
            x1s[3 * u + 1] = t[3 * u + 1] * sh.x;
            x1s[3 * u + 2] = t[3 * u + 2] * sh.x;
        }
    }
    float uu = d * ((float)TBLM * 0.125f);
    int i0 = (int)uu;
    if (i0 < 0) i0 = 0;
    if (i0 > TBLM - 1) i0 = TBLM - 1;
    float f = uu - (float)i0;

    ull o0p[8];
    float o1[24];
    #pragma unroll
    for (int k = 0; k < 8; ++k) o0p[k] = pk2(0.f);
    #pragma unroll
    for (int k = 0; k < 24; ++k) o1[k] = 0.f;

    value_pass(g_Mv + i0 * 576, x0, dd, x1s, sh, o0p, o1);
    // acc *= (1-f); inputs *= f; second pass accumulates f-scaled row i0+1
    float omf = 1.0f - f;
    ull omfp = pk2(omf);
    #pragma unroll
    for (int k = 0; k < 8; ++k) o0p[k] = f2mul(o0p[k], omfp);
    #pragma unroll
    for (int k = 0; k < 24; ++k) o1[k] *= omf;
    #pragma unroll
    for (int u = 0; u < 16; ++u) x0[u] *= f;
    #pragma unroll
    for (int u = 0; u < 8; ++u) dd[u] *= f;
    #pragma unroll
    for (int k = 0; k < 24; ++k) x1s[k] *= f;
    value_pass(g_Mv + (i0 + 1) * 576, x0, dd, x1s, sh, o0p, o1);

    float* ob = out + dst * 40;
    #pragma unroll
    for (int k = 0; k < 8; ++k) {
        float2 q = upk(o0p[k]);
        atomicAdd(ob + 2 * k, q.x * fs);
        atomicAdd(ob + 2 * k + 1, q.y * fs);
    }
    #pragma unroll
    for (int k = 0; k < 24; ++k)
        atomicAdd(ob + 16 + k, o1[k] * fs);
}

// -------- epilogue: out[i] *= rsqrt(z[i])
__global__ void normalize(float* __restrict__ out, int n) {
    int i = blockIdx.x * 128 + threadIdx.x;
    if (i >= n) return;
    float zz = g_z[i];
    if (zz <= 0.f) zz = 1.f;
    float s = rsqrtf(zz);
    float4* o4 = reinterpret_cast<float4*>(out + i * 40);
    #pragma unroll
    for (int m = 0; m < 10; ++m) {
        float4 v = o4[m];
        v.x *= s; v.y *= s; v.z *= s; v.w *= s;
        o4[m] = v;
    }
}

extern "C" void kernel_launch(void* const* d_in, const int* in_sizes, int n_in,
                              void* d_out, int out_size) {
    const float* x   = (const float*)d_in[0];
    const int*   ei  = (const int*)d_in[1];
    const float* ea  = (const float*)d_in[2];
    const float* amf = (const float*)d_in[5];
    const float* Wq0 = (const float*)d_in[6];
    const float* Wq1 = (const float*)d_in[7];
    const float* Wk1 = (const float*)d_in[8];
    const float* Wk2 = (const float*)d_in[9];
    const float* Wv1 = (const float*)d_in[10];
    const float* Wv2 = (const float*)d_in[11];
    const float* Wd0 = (const float*)d_in[12];
    const float* Wd1 = (const float*)d_in[13];
    float* out = (float*)d_out;

    int n = in_sizes[0] / 40;
    int E = in_sizes[2] / 4;

    build_h<<<(TBLM + 1 + 255) / 256, 256>>>(Wk1, Wv1);
    build_M<<<((TBLM + 1) * 288 + 255) / 256, 256>>>(Wk2, Wv2);
    hist_kernel<<<(E + 255) / 256, 256>>>(amf, E);
    scan_kernel<<<1, 1024>>>(TBLM);
    scatter_kernel<<<(E + 255) / 256, 256>>>(ei, ea, amf, E);
    node_prep<<<(n + 127) / 128, 128>>>(x, Wq0, Wq1, Wd0, Wd1, out, n);
    edge_score<<<(E + 127) / 128, 128>>>(x, E);
    edge_value<<<(E + 127) / 128, 128>>>(x, out, E);
    normalize<<<(n + 127) / 128, 128>>>(out, n);
}

// round 12
// speedup vs baseline: 1.6791x; 1.0656x over previous
#include <cuda_runtime.h>
#include <math.h>

#define NMAX 10000
#define EMAX 160000
#define TBLM 4096
typedef unsigned long long ull;

// device scratch (no runtime allocation)
__device__ __align__(16) float g_p0[NMAX * 16];
__device__ __align__(16) float g_p1[NMAX * 24];
__device__ float g_z[NMAX];
__device__ __align__(16) float g_hk[(TBLM + 1) * 16];
__device__ __align__(16) float g_hv[(TBLM + 1) * 16];
__device__ __align__(16) float g_Mk[(TBLM + 1) * 576];  // M(d)[j] = hk(d) . Wk2col_j
__device__ __align__(16) float g_Mv[(TBLM + 1) * 576];
// edge sort (by d-bin) scratch
__device__ int g_cnt[TBLM];
__device__ int g_off[TBLM];
__device__ int g_src[EMAX];
__device__ int g_dst[EMAX];
__device__ __align__(16) float4 g_sea[EMAX];
__device__ float g_sd[EMAX];

// ---------- packed f32x2 primitives ----------
__device__ __forceinline__ ull pk2(float a) {
    ull r; asm("mov.b64 %0, {%1,%1};" : "=l"(r) : "f"(a)); return r;
}
__device__ __forceinline__ ull pk(float a, float b) {
    ull r; asm("mov.b64 %0, {%1,%2};" : "=l"(r) : "f"(a), "f"(b)); return r;
}
__device__ __forceinline__ float2 upk(ull a) {
    float2 f; asm("mov.b64 {%0,%1}, %2;" : "=f"(f.x), "=f"(f.y) : "l"(a)); return f;
}
__device__ __forceinline__ ull f2fma(ull a, ull b, ull c) {
    ull d; asm("fma.rn.f32x2 %0, %1, %2, %3;" : "=l"(d) : "l"(a), "l"(b), "l"(c)); return d;
}
__device__ __forceinline__ ull f2mul(ull a, ull b) {
    ull d; asm("mul.rn.f32x2 %0, %1, %2;" : "=l"(d) : "l"(a), "l"(b)); return d;
}

__device__ __forceinline__ void ld16(float o[16], const float* __restrict__ p) {
    const float4* p4 = reinterpret_cast<const float4*>(p);
    float4 t0 = p4[0], t1 = p4[1], t2 = p4[2], t3 = p4[3];
    o[0] = t0.x; o[1] = t0.y; o[2] = t0.z; o[3] = t0.w;
    o[4] = t1.x; o[5] = t1.y; o[6] = t1.z; o[7] = t1.w;
    o[8] = t2.x; o[9] = t2.y; o[10] = t2.z; o[11] = t2.w;
    o[12] = t3.x; o[13] = t3.y; o[14] = t3.z; o[15] = t3.w;
}
__device__ __forceinline__ void ld24(float o[24], const float* __restrict__ p) {
    const float4* p4 = reinterpret_cast<const float4*>(p);
    #pragma unroll
    for (int k = 0; k < 6; ++k) {
        float4 t = p4[k];
        o[4 * k] = t.x; o[4 * k + 1] = t.y; o[4 * k + 2] = t.z; o[4 * k + 3] = t.w;
    }
}

// -------- setup: radial h rows + zero hist
__global__ void build_h(const float* __restrict__ Wk1, const float* __restrict__ Wv1) {
    int i = blockIdx.x * 256 + threadIdx.x;
    if (i < TBLM) g_cnt[i] = 0;
    if (i > TBLM) return;
    float d = (float)i * (8.0f / (float)TBLM);
    float emb[16];
    #pragma unroll
    for (int b = 0; b < 16; ++b) {
        float cb = 0.47058824f * (float)(b + 1);
        float diff = (d - cb) * 2.125f;
        float q = 1.0f - diff * diff;
        emb[b] = (q > 0.f) ? 33.7342930f * expf(-2.0f / q) : 0.f;
    }
    #pragma unroll
    for (int c = 0; c < 16; ++c) {
        float sk = 0.f, sv = 0.f;
        #pragma unroll
        for (int b = 0; b < 16; ++b) {
            sk = fmaf(emb[b], Wk1[b * 16 + c], sk);
            sv = fmaf(emb[b], Wv1[b * 16 + c], sv);
        }
        sk *= 0.25f; sv *= 0.25f;
        g_hk[i * 16 + c] = sk / (1.f + expf(-sk));
        g_hv[i * 16 + c] = sv / (1.f + expf(-sv));
    }
}

// -------- build M tables: M[row][j] = h(row) . W[:, j]; thread does 4 consecutive j
__global__ void build_M(const float* __restrict__ Wk2, const float* __restrict__ Wv2) {
    int idx = blockIdx.x * 256 + threadIdx.x;
    int row = idx / 288;
    if (row > TBLM) return;
    int rem = idx % 288;
    int tbl = rem / 144;
    int j4 = (rem % 144) * 4;
    const float* h = (tbl ? g_hv : g_hk) + row * 16;
    const float* W = tbl ? Wv2 : Wk2;
    float a0 = 0.f, a1 = 0.f, a2 = 0.f, a3 = 0.f;
    #pragma unroll
    for (int c = 0; c < 16; ++c) {
        float hc = h[c];
        const float4 w = *reinterpret_cast<const float4*>(W + c * 576 + j4);
        a0 = fmaf(hc, w.x, a0); a1 = fmaf(hc, w.y, a1);
        a2 = fmaf(hc, w.z, a2); a3 = fmaf(hc, w.w, a3);
    }
    float* dst = (tbl ? g_Mv : g_Mk) + row * 576 + j4;
    *reinterpret_cast<float4*>(dst) = make_float4(a0, a1, a2, a3);
}

// -------- counting sort by d-bin
__global__ void hist_kernel(const float* __restrict__ amf, int E) {
    int e = blockIdx.x * 256 + threadIdx.x;
    if (e >= E) return;
    int b = (int)(amf[e] * ((float)TBLM * 0.125f));
    if (b < 0) b = 0;
    if (b > TBLM - 1) b = TBLM - 1;
    atomicAdd(&g_cnt[b], 1);
}
__global__ __launch_bounds__(1024) void scan_kernel(int n) {
    __shared__ int part[1024];
    int t = threadIdx.x;
    int chunk = (n + 1023) / 1024;
    int base = t * chunk;
    int s = 0;
    for (int i = 0; i < chunk; ++i) {
        int j = base + i;
        if (j < n) s += g_cnt[j];
    }
    part[t] = s;
    __syncthreads();
    for (int off = 1; off < 1024; off <<= 1) {
        int v = (t >= off) ? part[t - off] : 0;
        __syncthreads();
        part[t] += v;
        __syncthreads();
    }
    int run = (t > 0) ? part[t - 1] : 0;
    for (int i = 0; i < chunk; ++i) {
        int j = base + i;
        if (j < n) {
            int c = g_cnt[j];
            g_off[j] = run;
            run += c;
        }
    }
}
__global__ void scatter_kernel(const int* __restrict__ ei, const float* __restrict__ ea,
                               const float* __restrict__ amf, int E) {
    int e = blockIdx.x * 256 + threadIdx.x;
    if (e >= E) return;
    float d = amf[e];
    int b = (int)(d * ((float)TBLM * 0.125f));
    if (b < 0) b = 0;
    if (b > TBLM - 1) b = TBLM - 1;
    int pos = atomicAdd(&g_off[b], 1);
    g_src[pos] = ei[e];
    g_dst[pos] = ei[E + e];
    g_sea[pos] = reinterpret_cast<const float4*>(ea)[e];
    g_sd[pos] = d;
}

// -------- per-node p0/p1 = x(WqWd) with norms folded; zero z and out
__global__ __launch_bounds__(128) void node_prep(
    const float* __restrict__ x,
    const float* __restrict__ Wq0, const float* __restrict__ Wq1,
    const float* __restrict__ Wd0, const float* __restrict__ Wd1,
    float* __restrict__ out, int n) {
    __shared__ float C0[256];
    __shared__ float C1[64];
    int t = threadIdx.x;
    for (int idx = t; idx < 256; idx += blockDim.x) {
        int u = idx >> 4, v = idx & 15;
        float s = 0.f;
        #pragma unroll
        for (int w = 0; w < 16; ++w) s = fmaf(Wq0[u * 16 + w], Wd0[w * 16 + v], s);
        C0[idx] = s * 0.25f;
    }
    if (t < 64) {
        int u = t >> 3, v = t & 7;
        float s = 0.f;
        #pragma unroll
        for (int w = 0; w < 8; ++w) s = fmaf(Wq1[u * 8 + w], Wd1[w * 8 + v], s);
        C1[t] = s * 0.2041241452f;  // 1/(sqrt(8)*sqrt(3))
    }
    __syncthreads();
    int i = blockIdx.x * blockDim.x + t;
    if (i >= n) return;

    float x0[16];
    #pragma unroll
    for (int u = 0; u < 16; ++u) x0[u] = x[i * 40 + u];
    #pragma unroll
    for (int v = 0; v < 16; ++v) {
        float s = 0.f;
        #pragma unroll
        for (int u = 0; u < 16; ++u) s = fmaf(x0[u], C0[u * 16 + v], s);
        g_p0[i * 16 + v] = s;
    }
    float x1[24];
    #pragma unroll
    for (int k = 0; k < 24; ++k) x1[k] = x[i * 40 + 16 + k];
    #pragma unroll
    for (int v = 0; v < 8; ++v) {
        #pragma unroll
        for (int c = 0; c < 3; ++c) {
            float s = 0.f;
            #pragma unroll
            for (int u = 0; u < 8; ++u) s = fmaf(x1[u * 3 + c], C1[u * 8 + v], s);
            g_p1[i * 24 + v * 3 + c] = s;
        }
    }
    g_z[i] = 0.f;
    float4 z4 = make_float4(0.f, 0.f, 0.f, 0.f);
    float4* o4 = reinterpret_cast<float4*>(out + i * 40);
    #pragma unroll
    for (int m = 0; m < 10; ++m) o4[m] = z4;
}

// -------- score pass over one M row
__device__ __forceinline__ float score_pass(
    const float* __restrict__ M, const float x0[16], const ull p0p[8],
    const ull rp[4], const float dd[8], const float x1s[24],
    const float p1[24], float sh0) {
    const ulonglong2* M2 = reinterpret_cast<const ulonglong2*>(M);
    ull acc = pk2(0.f);
    // B1: j=u*16+w, score += (x0u*sh0) * (p0 . Mrow_u)
    #pragma unroll
    for (int u = 0; u < 16; ++u) {
        ulonglong2 c0 = M2[u * 4], c1 = M2[u * 4 + 1], c2 = M2[u * 4 + 2], c3 = M2[u * 4 + 3];
        ull t = f2mul(p0p[0], c0.x);
        t = f2fma(p0p[1], c0.y, t); t = f2fma(p0p[2], c1.x, t); t = f2fma(p0p[3], c1.y, t);
        t = f2fma(p0p[4], c2.x, t); t = f2fma(p0p[5], c2.y, t);
        t = f2fma(p0p[6], c3.x, t); t = f2fma(p0p[7], c3.y, t);
        acc = f2fma(pk2(x0[u] * sh0), t, acc);
    }
    // B2: j=256+u*8+w, score += x0u * (r . Mrow_u)
    #pragma unroll
    for (int u = 0; u < 16; ++u) {
        ulonglong2 c0 = M2[64 + u * 2], c1 = M2[64 + u * 2 + 1];
        ull t = f2mul(rp[0], c0.x);
        t = f2fma(rp[1], c0.y, t); t = f2fma(rp[2], c1.x, t); t = f2fma(rp[3], c1.y, t);
        acc = f2fma(pk2(x0[u]), t, acc);
    }
    // B4: j=448+u*16+w, score += dd_u * (p0 . Mrow_u)
    #pragma unroll
    for (int u = 0; u < 8; ++u) {
        ulonglong2 c0 = M2[112 + u * 4], c1 = M2[112 + u * 4 + 1],
                   c2 = M2[112 + u * 4 + 2], c3 = M2[112 + u * 4 + 3];
        ull t = f2mul(p0p[0], c0.x);
        t = f2fma(p0p[1], c0.y, t); t = f2fma(p0p[2], c1.x, t); t = f2fma(p0p[3], c1.y, t);
        t = f2fma(p0p[4], c2.x, t); t = f2fma(p0p[5], c2.y, t);
        t = f2fma(p0p[6], c3.x, t); t = f2fma(p0p[7], c3.y, t);
        acc = f2fma(pk2(dd[u]), t, acc);
    }
    // B3: j=384+u*8+w, score += sum_u x1s_u . (sum_w M3[u][w] p1_w)
    float s3 = 0.f;
    #pragma unroll
    for (int u = 0; u < 8; ++u) {
        const float4* m4 = reinterpret_cast<const float4*>(M + 384 + u * 8);
        float4 A = m4[0], B = m4[1];
        float tvx = A.x * p1[0] + A.y * p1[3] + A.z * p1[6] + A.w * p1[9]
                  + B.x * p1[12] + B.y * p1[15] + B.z * p1[18] + B.w * p1[21];
        float tvy = A.x * p1[1] + A.y * p1[4] + A.z * p1[7] + A.w * p1[10]
                  + B.x * p1[13] + B.y * p1[16] + B.z * p1[19] + B.w * p1[22];
        float tvz = A.x * p1[2] + A.y * p1[5] + A.z * p1[8] + A.w * p1[11]
                  + B.x * p1[14] + B.y * p1[17] + B.z * p1[20] + B.w * p1[23];
        s3 += x1s[3 * u] * tvx + x1s[3 * u + 1] * tvy + x1s[3 * u + 2] * tvz;
    }
    float2 a2 = upk(acc);
    return a2.x + a2.y + s3;
}

// -------- value pass over one M row: accumulate o0 (packed) and o1 (scalar)
__device__ __forceinline__ void value_pass(
    const float* __restrict__ M, const float x0[16], const float dd[8],
    const float x1s[24], float4 sh, ull o0p[8], float o1[24]) {
    const ulonglong2* M2 = reinterpret_cast<const ulonglong2*>(M);
    // B1: o0[w] += (x0u*sh0) * M1[u][w]
    #pragma unroll
    for (int u = 0; u < 16; ++u) {
        ull fa = pk2(x0[u] * sh.x);
        ulonglong2 c0 = M2[u * 4], c1 = M2[u * 4 + 1], c2 = M2[u * 4 + 2], c3 = M2[u * 4 + 3];
        o0p[0] = f2fma(fa, c0.x, o0p[0]); o0p[1] = f2fma(fa, c0.y, o0p[1]);
        o0p[2] = f2fma(fa, c1.x, o0p[2]); o0p[3] = f2fma(fa, c1.y, o0p[3]);
        o0p[4] = f2fma(fa, c2.x, o0p[4]); o0p[5] = f2fma(fa, c2.y, o0p[5]);
        o0p[6] = f2fma(fa, c3.x, o0p[6]); o0p[7] = f2fma(fa, c3.y, o0p[7]);
    }
    // B4: o0[w] += dd_u * M4[u][w]
    #pragma unroll
    for (int u = 0; u < 8; ++u) {
        ull fa = pk2(dd[u]);
        ulonglong2 c0 = M2[112 + u * 4], c1 = M2[112 + u * 4 + 1],
                   c2 = M2[112 + u * 4 + 2], c3 = M2[112 + u * 4 + 3];
        o0p[0] = f2fma(fa, c0.x, o0p[0]); o0p[1] = f2fma(fa, c0.y, o0p[1]);
        o0p[2] = f2fma(fa, c1.x, o0p[2]); o0p[3] = f2fma(fa, c1.y, o0p[3]);
        o0p[4] = f2fma(fa, c2.x, o0p[4]); o0p[5] = f2fma(fa, c2.y, o0p[5]);
        o0p[6] = f2fma(fa, c3.x, o0p[6]); o0p[7] = f2fma(fa, c3.y, o0p[7]);
    }
    // B2: A[w] = sum_u x0u M2[u][w]
    ull Ap[4] = {pk2(0.f), pk2(0.f), pk2(0.f), pk2(0.f)};
    #pragma unroll
    for (int u = 0; u < 16; ++u) {
        ull fa = pk2(x0[u]);
        ulonglong2 c0 = M2[64 + u * 2], c1 = M2[64 + u * 2 + 1];
        Ap[0] = f2fma(fa, c0.x, Ap[0]); Ap[1] = f2fma(fa, c0.y, Ap[1]);
        Ap[2] = f2fma(fa, c1.x, Ap[2]); Ap[3] = f2fma(fa, c1.y, Ap[3]);
    }
    // B3: o1[w,:] += M3[u][w] * x1s[u,:]
    #pragma unroll
    for (int u = 0; u < 8; ++u) {
        const float4* m4 = reinterpret_cast<const float4*>(M + 384 + u * 8);
        float4 A = m4[0], B = m4[1];
        float xa = x1s[3 * u], xb = x1s[3 * u + 1], xc = x1s[3 * u + 2];
        o1[0] = fmaf(A.x, xa, o1[0]);  o1[1] = fmaf(A.x, xb, o1[1]);  o1[2] = fmaf(A.x, xc, o1[2]);
        o1[3] = fmaf(A.y, xa, o1[3]);  o1[4] = fmaf(A.y, xb, o1[4]);  o1[5] = fmaf(A.y, xc, o1[5]);
        o1[6] = fmaf(A.z, xa, o1[6]);  o1[7] = fmaf(A.z, xb, o1[7]);  o1[8] = fmaf(A.z, xc, o1[8]);
        o1[9] = fmaf(A.w, xa, o1[9]);  o1[10] = fmaf(A.w, xb, o1[10]); o1[11] = fmaf(A.w, xc, o1[11]);
        o1[12] = fmaf(B.x, xa, o1[12]); o1[13] = fmaf(B.x, xb, o1[13]); o1[14] = fmaf(B.x, xc, o1[14]);
        o1[15] = fmaf(B.y, xa, o1[15]); o1[16] = fmaf(B.y, xb, o1[16]); o1[17] = fmaf(B.y, xc, o1[17]);
        o1[18] = fmaf(B.z, xa, o1[18]); o1[19] = fmaf(B.z, xb, o1[19]); o1[20] = fmaf(B.z, xc, o1[20]);
        o1[21] = fmaf(B.w, xa, o1[21]); o1[22] = fmaf(B.w, xb, o1[22]); o1[23] = fmaf(B.w, xc, o1[23]);
    }
    // A-term: o1[w,:] += A[w] * sh1
    #pragma unroll
    for (int k = 0; k < 4; ++k) {
        float2 a2 = upk(Ap[k]);
        int w0 = 2 * k, w1 = 2 * k + 1;
        o1[3 * w0] = fmaf(a2.x, sh.y, o1[3 * w0]);
        o1[3 * w0 + 1] = fmaf(a2.x, sh.z, o1[3 * w0 + 1]);
        o1[3 * w0 + 2] = fmaf(a2.x, sh.w, o1[3 * w0 + 2]);
        o1[3 * w1] = fmaf(a2.y, sh.y, o1[3 * w1]);
        o1[3 * w1 + 1] = fmaf(a2.y, sh.z, o1[3 * w1 + 1]);
        o1[3 * w1 + 2] = fmaf(a2.y, sh.w, o1[3 * w1 + 2]);
    }
}

// -------- fused edge kernel: score + value, one edge/thread (d-sorted)
__global__ __launch_bounds__(128) void edge_fused(
    const float* __restrict__ x, float* __restrict__ out, int E) {
    int e = blockIdx.x * 128 + threadIdx.x;
    if (e >= E) return;
    int src = g_src[e], dst = g_dst[e];
    float4 sh = g_sea[e];
    float d = g_sd[e];

    // shared per-edge gathers
    float x0[16]; ld16(x0, x + src * 40);
    float x1s[24], dd[8];
    {
        float t[24]; ld24(t, x + src * 40 + 16);
        #pragma unroll
        for (int u = 0; u < 8; ++u) {
            dd[u] = (t[3 * u] * sh.y + t[3 * u + 1] * sh.z + t[3 * u + 2] * sh.w) * 0.57735027f;
            x1s[3 * u] = t[3 * u] * sh.x;
            x1s[3 * u + 1] = t[3 * u + 1] * sh.x;
            x1s[3 * u + 2] = t[3 * u + 2] * sh.x;
        }
    }
    float uu = d * ((float)TBLM * 0.125f);
    int i0 = (int)uu;
    if (i0 < 0) i0 = 0;
    if (i0 > TBLM - 1) i0 = TBLM - 1;
    float f = uu - (float)i0;

    // ---- score phase (p0/p1/rp live only here)
    float ev;
    {
        ull p0p[8];
        {
            float p0[16]; ld16(p0, g_p0 + dst * 16);
            #pragma unroll
            for (int k = 0; k < 8; ++k) p0p[k] = pk(p0[2 * k], p0[2 * k + 1]);
        }
        float p1[24]; ld24(p1, g_p1 + dst * 24);
        ull rp[4];
        #pragma unroll
        for (int k = 0; k < 4; ++k) {
            float r0 = p1[6 * k] * sh.y + p1[6 * k + 1] * sh.z + p1[6 * k + 2] * sh.w;
            float r1 = p1[6 * k + 3] * sh.y + p1[6 * k + 4] * sh.z + p1[6 * k + 5] * sh.w;
            rp[k] = pk(r0, r1);
        }
        float s0 = score_pass(g_Mk + i0 * 576, x0, p0p, rp, dd, x1s, p1, sh.x);
        float s1 = score_pass(g_Mk + (i0 + 1) * 576, x0, p0p, rp, dd, x1s, p1, sh.x);
        float score = (s0 + f * (s1 - s0)) * 0.0028527222f;  // 1/(4*sqrt(24)*sqrt(320))
        float tc = 10.0f * (1.0f - d * 0.125f);
        float cut = (tc > 0.f) ? __expf(-__frcp_rn(tc)) : 0.f;
        ev = cut * __expf(score);
    }
    atomicAdd(&g_z[dst], ev);
    float fs = sqrtf(ev) * 0.0510310363f;  // sqrt(ev)/(4*sqrt(24))

    // ---- value phase
    ull o0p[8];
    float o1[24];
    #pragma unroll
    for (int k = 0; k < 8; ++k) o0p[k] = pk2(0.f);
    #pragma unroll
    for (int k = 0; k < 24; ++k) o1[k] = 0.f;

    value_pass(g_Mv + i0 * 576, x0, dd, x1s, sh, o0p, o1);
    float omf = 1.0f - f;
    ull omfp = pk2(omf);
    #pragma unroll
    for (int k = 0; k < 8; ++k) o0p[k] = f2mul(o0p[k], omfp);
    #pragma unroll
    for (int k = 0; k < 24; ++k) o1[k] *= omf;
    #pragma unroll
    for (int u = 0; u < 16; ++u) x0[u] *= f;
    #pragma unroll
    for (int u = 0; u < 8; ++u) dd[u] *= f;
    #pragma unroll
    for (int k = 0; k < 24; ++k) x1s[k] *= f;
    value_pass(g_Mv + (i0 + 1) * 576, x0, dd, x1s, sh, o0p, o1);

    float* ob = out + dst * 40;
    #pragma unroll
    for (int k = 0; k < 8; ++k) {
        float2 q = upk(o0p[k]);
        atomicAdd(ob + 2 * k, q.x * fs);
        atomicAdd(ob + 2 * k + 1, q.y * fs);
    }
    #pragma unroll
    for (int k = 0; k < 24; ++k)
        atomicAdd(ob + 16 + k, o1[k] * fs);
}

// -------- epilogue: out[i] *= rsqrt(z[i])
__global__ void normalize(float* __restrict__ out, int n) {
    int i = blockIdx.x * 128 + threadIdx.x;
    if (i >= n) return;
    float zz = g_z[i];
    if (zz <= 0.f) zz = 1.f;
    float s = rsqrtf(zz);
    float4* o4 = reinterpret_cast<float4*>(out + i * 40);
    #pragma unroll
    for (int m = 0; m < 10; ++m) {
        float4 v = o4[m];
        v.x *= s; v.y *= s; v.z *= s; v.w *= s;
        o4[m] = v;
    }
}

extern "C" void kernel_launch(void* const* d_in, const int* in_sizes, int n_in,
                              void* d_out, int out_size) {
    const float* x   = (const float*)d_in[0];
    const int*   ei  = (const int*)d_in[1];
    const float* ea  = (const float*)d_in[2];
    const float* amf = (const float*)d_in[5];
    const float* Wq0 = (const float*)d_in[6];
    const float* Wq1 = (const float*)d_in[7];
    const float* Wk1 = (const float*)d_in[8];
    const float* Wk2 = (const float*)d_in[9];
    const float* Wv1 = (const float*)d_in[10];
    const float* Wv2 = (const float*)d_in[11];
    const float* Wd0 = (const float*)d_in[12];
    const float* Wd1 = (const float*)d_in[13];
    float* out = (float*)d_out;

    int n = in_sizes[0] / 40;
    int E = in_sizes[2] / 4;

    build_h<<<(TBLM + 1 + 255) / 256, 256>>>(Wk1, Wv1);
    build_M<<<((TBLM + 1) * 288 + 255) / 256, 256>>>(Wk2, Wv2);
    hist_kernel<<<(E + 255) / 256, 256>>>(amf, E);
    scan_kernel<<<1, 1024>>>(TBLM);
    scatter_kernel<<<(E + 255) / 256, 256>>>(ei, ea, amf, E);
    node_prep<<<(n + 127) / 128, 128>>>(x, Wq0, Wq1, Wd0, Wd1, out, n);
    edge_fused<<<(E + 127) / 128, 128>>>(x, out, E);
    normalize<<<(n + 127) / 128, 128>>>(out, n);
}

// round 13
// speedup vs baseline: 1.9056x; 1.1349x over previous
#include <cuda_runtime.h>
#include <math.h>

#define NMAX 10000
#define EMAX 160000
#define TBLM 4096
typedef unsigned long long ull;

// device scratch (no runtime allocation)
__device__ __align__(16) float g_p0[NMAX * 16];
__device__ __align__(16) float g_p1[NMAX * 24];
__device__ float g_z[NMAX];
__device__ __align__(16) float g_hk[(TBLM + 1) * 16];
__device__ __align__(16) float g_hv[(TBLM + 1) * 16];
__device__ __align__(16) float g_Mk[(TBLM + 1) * 576];  // M(d)[j] = hk(d) . Wk2col_j
__device__ __align__(16) float g_Mv[(TBLM + 1) * 576];
// edge sort (by d-bin) scratch
__device__ int g_cnt[TBLM];
__device__ int g_off[TBLM];
__device__ int g_src[EMAX];
__device__ int g_dst[EMAX];
__device__ __align__(16) float4 g_sea[EMAX];
__device__ float g_sd[EMAX];

// ---------- packed f32x2 primitives ----------
__device__ __forceinline__ ull pk2(float a) {
    ull r; asm("mov.b64 %0, {%1,%1};" : "=l"(r) : "f"(a)); return r;
}
__device__ __forceinline__ ull pk(float a, float b) {
    ull r; asm("mov.b64 %0, {%1,%2};" : "=l"(r) : "f"(a), "f"(b)); return r;
}
__device__ __forceinline__ float2 upk(ull a) {
    float2 f; asm("mov.b64 {%0,%1}, %2;" : "=f"(f.x), "=f"(f.y) : "l"(a)); return f;
}
__device__ __forceinline__ ull f2fma(ull a, ull b, ull c) {
    ull d; asm("fma.rn.f32x2 %0, %1, %2, %3;" : "=l"(d) : "l"(a), "l"(b), "l"(c)); return d;
}
__device__ __forceinline__ ull f2mul(ull a, ull b) {
    ull d; asm("mul.rn.f32x2 %0, %1, %2;" : "=l"(d) : "l"(a), "l"(b)); return d;
}
// vector reduction atomic: out[0..3] += {a,b,c,d} (16B-aligned)
__device__ __forceinline__ void red4(float* p, float a, float b, float c, float d) {
    asm volatile("red.global.add.v4.f32 [%0], {%1,%2,%3,%4};"
                 :: "l"(p), "f"(a), "f"(b), "f"(c), "f"(d) : "memory");
}

__device__ __forceinline__ void ld16(float o[16], const float* __restrict__ p) {
    const float4* p4 = reinterpret_cast<const float4*>(p);
    float4 t0 = p4[0], t1 = p4[1], t2 = p4[2], t3 = p4[3];
    o[0] = t0.x; o[1] = t0.y; o[2] = t0.z; o[3] = t0.w;
    o[4] = t1.x; o[5] = t1.y; o[6] = t1.z; o[7] = t1.w;
    o[8] = t2.x; o[9] = t2.y; o[10] = t2.z; o[11] = t2.w;
    o[12] = t3.x; o[13] = t3.y; o[14] = t3.z; o[15] = t3.w;
}
__device__ __forceinline__ void ld24(float o[24], const float* __restrict__ p) {
    const float4* p4 = reinterpret_cast<const float4*>(p);
    #pragma unroll
    for (int k = 0; k < 6; ++k) {
        float4 t = p4[k];
        o[4 * k] = t.x; o[4 * k + 1] = t.y; o[4 * k + 2] = t.z; o[4 * k + 3] = t.w;
    }
}

// -------- stage 1: radial h rows + zero hist
__global__ void build_h(const float* __restrict__ Wk1, const float* __restrict__ Wv1) {
    int i = blockIdx.x * 256 + threadIdx.x;
    if (i < TBLM) g_cnt[i] = 0;
    if (i > TBLM) return;
    float d = (float)i * (8.0f / (float)TBLM);
    float emb[16];
    #pragma unroll
    for (int b = 0; b < 16; ++b) {
        float cb = 0.47058824f * (float)(b + 1);
        float diff = (d - cb) * 2.125f;
        float q = 1.0f - diff * diff;
        emb[b] = (q > 0.f) ? 33.7342930f * expf(-2.0f / q) : 0.f;
    }
    #pragma unroll
    for (int c = 0; c < 16; ++c) {
        float sk = 0.f, sv = 0.f;
        #pragma unroll
        for (int b = 0; b < 16; ++b) {
            sk = fmaf(emb[b], Wk1[b * 16 + c], sk);
            sv = fmaf(emb[b], Wv1[b * 16 + c], sv);
        }
        sk *= 0.25f; sv *= 0.25f;
        g_hk[i * 16 + c] = sk / (1.f + expf(-sk));
        g_hv[i * 16 + c] = sv / (1.f + expf(-sv));
    }
}

// -------- stage 2: histogram of d-bins
__global__ void hist_kernel(const float* __restrict__ amf, int E) {
    int e = blockIdx.x * 256 + threadIdx.x;
    if (e >= E) return;
    int b = (int)(amf[e] * ((float)TBLM * 0.125f));
    if (b < 0) b = 0;
    if (b > TBLM - 1) b = TBLM - 1;
    atomicAdd(&g_cnt[b], 1);
}
// -------- stage 3: exclusive scan of bins
__global__ __launch_bounds__(1024) void scan_kernel(int n) {
    __shared__ int part[1024];
    int t = threadIdx.x;
    int chunk = (n + 1023) / 1024;
    int base = t * chunk;
    int s = 0;
    for (int i = 0; i < chunk; ++i) {
        int j = base + i;
        if (j < n) s += g_cnt[j];
    }
    part[t] = s;
    __syncthreads();
    for (int off = 1; off < 1024; off <<= 1) {
        int v = (t >= off) ? part[t - off] : 0;
        __syncthreads();
        part[t] += v;
        __syncthreads();
    }
    int run = (t > 0) ? part[t - 1] : 0;
    for (int i = 0; i < chunk; ++i) {
        int j = base + i;
        if (j < n) {
            int c = g_cnt[j];
            g_off[j] = run;
            run += c;
        }
    }
}

// -------- stage 4 (mega): scatter + node_prep + build_M by block role
#define NB_SCAT ((EMAX + 255) / 256)
__global__ __launch_bounds__(256) void mega_kernel(
    const float* __restrict__ x, const int* __restrict__ ei,
    const float* __restrict__ ea, const float* __restrict__ amf,
    const float* __restrict__ Wq0, const float* __restrict__ Wq1,
    const float* __restrict__ Wd0, const float* __restrict__ Wd1,
    const float* __restrict__ Wk2, const float* __restrict__ Wv2,
    float* __restrict__ out, int n, int E, int nbScat, int nbNode) {
    int b = blockIdx.x;
    int t = threadIdx.x;
    if (b < nbScat) {
        // ---- scatter (edge reorder by d-bin)
        int e = b * 256 + t;
        if (e >= E) return;
        float d = amf[e];
        int bin = (int)(d * ((float)TBLM * 0.125f));
        if (bin < 0) bin = 0;
        if (bin > TBLM - 1) bin = TBLM - 1;
        int pos = atomicAdd(&g_off[bin], 1);
        g_src[pos] = ei[e];
        g_dst[pos] = ei[E + e];
        g_sea[pos] = reinterpret_cast<const float4*>(ea)[e];
        g_sd[pos] = d;
        return;
    }
    if (b < nbScat + nbNode) {
        // ---- node_prep
        __shared__ float C0[256];
        __shared__ float C1[64];
        {
            int u = t >> 4, v = t & 15;
            float s = 0.f;
            #pragma unroll
            for (int w = 0; w < 16; ++w) s = fmaf(Wq0[u * 16 + w], Wd0[w * 16 + v], s);
            C0[t] = s * 0.25f;
        }
        if (t < 64) {
            int u = t >> 3, v = t & 7;
            float s = 0.f;
            #pragma unroll
            for (int w = 0; w < 8; ++w) s = fmaf(Wq1[u * 8 + w], Wd1[w * 8 + v], s);
            C1[t] = s * 0.2041241452f;  // 1/(sqrt(8)*sqrt(3))
        }
        __syncthreads();
        int i = (b - nbScat) * 256 + t;
        if (i >= n) return;
        float x0[16];
        #pragma unroll
        for (int u = 0; u < 16; ++u) x0[u] = x[i * 40 + u];
        #pragma unroll
        for (int v = 0; v < 16; ++v) {
            float s = 0.f;
            #pragma unroll
            for (int u = 0; u < 16; ++u) s = fmaf(x0[u], C0[u * 16 + v], s);
            g_p0[i * 16 + v] = s;
        }
        float x1[24];
        #pragma unroll
        for (int k = 0; k < 24; ++k) x1[k] = x[i * 40 + 16 + k];
        #pragma unroll
        for (int v = 0; v < 8; ++v) {
            #pragma unroll
            for (int c = 0; c < 3; ++c) {
                float s = 0.f;
                #pragma unroll
                for (int u = 0; u < 8; ++u) s = fmaf(x1[u * 3 + c], C1[u * 8 + v], s);
                g_p1[i * 24 + v * 3 + c] = s;
            }
        }
        g_z[i] = 0.f;
        float4 z4 = make_float4(0.f, 0.f, 0.f, 0.f);
        float4* o4 = reinterpret_cast<float4*>(out + i * 40);
        #pragma unroll
        for (int m = 0; m < 10; ++m) o4[m] = z4;
        return;
    }
    // ---- build_M: idx over (TBLM+1)*288 work items
    int idx = (b - nbScat - nbNode) * 256 + t;
    int row = idx / 288;
    if (row > TBLM) return;
    int rem = idx % 288;
    int tbl = rem / 144;
    int j4 = (rem % 144) * 4;
    const float* h = (tbl ? g_hv : g_hk) + row * 16;
    const float* W = tbl ? Wv2 : Wk2;
    float a0 = 0.f, a1 = 0.f, a2 = 0.f, a3 = 0.f;
    #pragma unroll
    for (int c = 0; c < 16; ++c) {
        float hc = h[c];
        const float4 w = *reinterpret_cast<const float4*>(W + c * 576 + j4);
        a0 = fmaf(hc, w.x, a0); a1 = fmaf(hc, w.y, a1);
        a2 = fmaf(hc, w.z, a2); a3 = fmaf(hc, w.w, a3);
    }
    float* dst = (tbl ? g_Mv : g_Mk) + row * 576 + j4;
    *reinterpret_cast<float4*>(dst) = make_float4(a0, a1, a2, a3);
}

// -------- score pass over one M row
__device__ __forceinline__ float score_pass(
    const float* __restrict__ M, const float x0[16], const ull p0p[8],
    const ull rp[4], const float dd[8], const float x1s[24],
    const float p1[24], float sh0) {
    const ulonglong2* M2 = reinterpret_cast<const ulonglong2*>(M);
    ull acc = pk2(0.f);
    // B1: j=u*16+w, score += (x0u*sh0) * (p0 . Mrow_u)
    #pragma unroll
    for (int u = 0; u < 16; ++u) {
        ulonglong2 c0 = M2[u * 4], c1 = M2[u * 4 + 1], c2 = M2[u * 4 + 2], c3 = M2[u * 4 + 3];
        ull t = f2mul(p0p[0], c0.x);
        t = f2fma(p0p[1], c0.y, t); t = f2fma(p0p[2], c1.x, t); t = f2fma(p0p[3], c1.y, t);
        t = f2fma(p0p[4], c2.x, t); t = f2fma(p0p[5], c2.y, t);
        t = f2fma(p0p[6], c3.x, t); t = f2fma(p0p[7], c3.y, t);
        acc = f2fma(pk2(x0[u] * sh0), t, acc);
    }
    // B2: j=256+u*8+w, score += x0u * (r . Mrow_u)
    #pragma unroll
    for (int u = 0; u < 16; ++u) {
        ulonglong2 c0 = M2[64 + u * 2], c1 = M2[64 + u * 2 + 1];
        ull t = f2mul(rp[0], c0.x);
        t = f2fma(rp[1], c0.y, t); t = f2fma(rp[2], c1.x, t); t = f2fma(rp[3], c1.y, t);
        acc = f2fma(pk2(x0[u]), t, acc);
    }
    // B4: j=448+u*16+w, score += dd_u * (p0 . Mrow_u)
    #pragma unroll
    for (int u = 0; u < 8; ++u) {
        ulonglong2 c0 = M2[112 + u * 4], c1 = M2[112 + u * 4 + 1],
                   c2 = M2[112 + u * 4 + 2], c3 = M2[112 + u * 4 + 3];
        ull t = f2mul(p0p[0], c0.x);
        t = f2fma(p0p[1], c0.y, t); t = f2fma(p0p[2], c1.x, t); t = f2fma(p0p[3], c1.y, t);
        t = f2fma(p0p[4], c2.x, t); t = f2fma(p0p[5], c2.y, t);
        t = f2fma(p0p[6], c3.x, t); t = f2fma(p0p[7], c3.y, t);
        acc = f2fma(pk2(dd[u]), t, acc);
    }
    // B3: j=384+u*8+w, score += sum_u x1s_u . (sum_w M3[u][w] p1_w)
    float s3 = 0.f;
    #pragma unroll
    for (int u = 0; u < 8; ++u) {
        const float4* m4 = reinterpret_cast<const float4*>(M + 384 + u * 8);
        float4 A = m4[0], B = m4[1];
        float tvx = A.x * p1[0] + A.y * p1[3] + A.z * p1[6] + A.w * p1[9]
                  + B.x * p1[12] + B.y * p1[15] + B.z * p1[18] + B.w * p1[21];
        float tvy = A.x * p1[1] + A.y * p1[4] + A.z * p1[7] + A.w * p1[10]
                  + B.x * p1[13] + B.y * p1[16] + B.z * p1[19] + B.w * p1[22];
        float tvz = A.x * p1[2] + A.y * p1[5] + A.z * p1[8] + A.w * p1[11]
                  + B.x * p1[14] + B.y * p1[17] + B.z * p1[20] + B.w * p1[23];
        s3 += x1s[3 * u] * tvx + x1s[3 * u + 1] * tvy + x1s[3 * u + 2] * tvz;
    }
    float2 a2 = upk(acc);
    return a2.x + a2.y + s3;
}

// -------- value pass over one M row: accumulate o0 (packed) and o1 (scalar)
__device__ __forceinline__ void value_pass(
    const float* __restrict__ M, const float x0[16], const float dd[8],
    const float x1s[24], float4 sh, ull o0p[8], float o1[24]) {
    const ulonglong2* M2 = reinterpret_cast<const ulonglong2*>(M);
    // B1: o0[w] += (x0u*sh0) * M1[u][w]
    #pragma unroll
    for (int u = 0; u < 16; ++u) {
        ull fa = pk2(x0[u] * sh.x);
        ulonglong2 c0 = M2[u * 4], c1 = M2[u * 4 + 1], c2 = M2[u * 4 + 2], c3 = M2[u * 4 + 3];
        o0p[0] = f2fma(fa, c0.x, o0p[0]); o0p[1] = f2fma(fa, c0.y, o0p[1]);
        o0p[2] = f2fma(fa, c1.x, o0p[2]); o0p[3] = f2fma(fa, c1.y, o0p[3]);
        o0p[4] = f2fma(fa, c2.x, o0p[4]); o0p[5] = f2fma(fa, c2.y, o0p[5]);
        o0p[6] = f2fma(fa, c3.x, o0p[6]); o0p[7] = f2fma(fa, c3.y, o0p[7]);
    }
    // B4: o0[w] += dd_u * M4[u][w]
    #pragma unroll
    for (int u = 0; u < 8; ++u) {
        ull fa = pk2(dd[u]);
        ulonglong2 c0 = M2[112 + u * 4], c1 = M2[112 + u * 4 + 1],
                   c2 = M2[112 + u * 4 + 2], c3 = M2[112 + u * 4 + 3];
        o0p[0] = f2fma(fa, c0.x, o0p[0]); o0p[1] = f2fma(fa, c0.y, o0p[1]);
        o0p[2] = f2fma(fa, c1.x, o0p[2]); o0p[3] = f2fma(fa, c1.y, o0p[3]);
        o0p[4] = f2fma(fa, c2.x, o0p[4]); o0p[5] = f2fma(fa, c2.y, o0p[5]);
        o0p[6] = f2fma(fa, c3.x, o0p[6]); o0p[7] = f2fma(fa, c3.y, o0p[7]);
    }
    // B2: A[w] = sum_u x0u M2[u][w]
    ull Ap[4] = {pk2(0.f), pk2(0.f), pk2(0.f), pk2(0.f)};
    #pragma unroll
    for (int u = 0; u < 16; ++u) {
        ull fa = pk2(x0[u]);
        ulonglong2 c0 = M2[64 + u * 2], c1 = M2[64 + u * 2 + 1];
        Ap[0] = f2fma(fa, c0.x, Ap[0]); Ap[1] = f2fma(fa, c0.y, Ap[1]);
        Ap[2] = f2fma(fa, c1.x, Ap[2]); Ap[3] = f2fma(fa, c1.y, Ap[3]);
    }
    // B3: o1[w,:] += M3[u][w] * x1s[u,:]
    #pragma unroll
    for (int u = 0; u < 8; ++u) {
        const float4* m4 = reinterpret_cast<const float4*>(M + 384 + u * 8);
        float4 A = m4[0], B = m4[1];
        float xa = x1s[3 * u], xb = x1s[3 * u + 1], xc = x1s[3 * u + 2];
        o1[0] = fmaf(A.x, xa, o1[0]);  o1[1] = fmaf(A.x, xb, o1[1]);  o1[2] = fmaf(A.x, xc, o1[2]);
        o1[3] = fmaf(A.y, xa, o1[3]);  o1[4] = fmaf(A.y, xb, o1[4]);  o1[5] = fmaf(A.y, xc, o1[5]);
        o1[6] = fmaf(A.z, xa, o1[6]);  o1[7] = fmaf(A.z, xb, o1[7]);  o1[8] = fmaf(A.z, xc, o1[8]);
        o1[9] = fmaf(A.w, xa, o1[9]);  o1[10] = fmaf(A.w, xb, o1[10]); o1[11] = fmaf(A.w, xc, o1[11]);
        o1[12] = fmaf(B.x, xa, o1[12]); o1[13] = fmaf(B.x, xb, o1[13]); o1[14] = fmaf(B.x, xc, o1[14]);
        o1[15] = fmaf(B.y, xa, o1[15]); o1[16] = fmaf(B.y, xb, o1[16]); o1[17] = fmaf(B.y, xc, o1[17]);
        o1[18] = fmaf(B.z, xa, o1[18]); o1[19] = fmaf(B.z, xb, o1[19]); o1[20] = fmaf(B.z, xc, o1[20]);
        o1[21] = fmaf(B.w, xa, o1[21]); o1[22] = fmaf(B.w, xb, o1[22]); o1[23] = fmaf(B.w, xc, o1[23]);
    }
    // A-term: o1[w,:] += A[w] * sh1
    #pragma unroll
    for (int k = 0; k < 4; ++k) {
        float2 a2 = upk(Ap[k]);
        int w0 = 2 * k, w1 = 2 * k + 1;
        o1[3 * w0] = fmaf(a2.x, sh.y, o1[3 * w0]);
        o1[3 * w0 + 1] = fmaf(a2.x, sh.z, o1[3 * w0 + 1]);
        o1[3 * w0 + 2] = fmaf(a2.x, sh.w, o1[3 * w0 + 2]);
        o1[3 * w1] = fmaf(a2.y, sh.y, o1[3 * w1]);
        o1[3 * w1 + 1] = fmaf(a2.y, sh.z, o1[3 * w1 + 1]);
        o1[3 * w1 + 2] = fmaf(a2.y, sh.w, o1[3 * w1 + 2]);
    }
}

// -------- fused edge kernel: score + value, one edge/thread (d-sorted)
__global__ __launch_bounds__(128) void edge_fused(
    const float* __restrict__ x, float* __restrict__ out, int E) {
    int e = blockIdx.x * 128 + threadIdx.x;
    if (e >= E) return;
    int src = g_src[e], dst = g_dst[e];
    float4 sh = g_sea[e];
    float d = g_sd[e];

    // shared per-edge gathers
    float x0[16]; ld16(x0, x + src * 40);
    float x1s[24], dd[8];
    {
        float t[24]; ld24(t, x + src * 40 + 16);
        #pragma unroll
        for (int u = 0; u < 8; ++u) {
            dd[u] = (t[3 * u] * sh.y + t[3 * u + 1] * sh.z + t[3 * u + 2] * sh.w) * 0.57735027f;
            x1s[3 * u] = t[3 * u] * sh.x;
            x1s[3 * u + 1] = t[3 * u + 1] * sh.x;
            x1s[3 * u + 2] = t[3 * u + 2] * sh.x;
        }
    }
    float uu = d * ((float)TBLM * 0.125f);
    int i0 = (int)uu;
    if (i0 < 0) i0 = 0;
    if (i0 > TBLM - 1) i0 = TBLM - 1;
    float f = uu - (float)i0;

    // ---- score phase (p0/p1/rp live only here)
    float ev;
    {
        ull p0p[8];
        {
            float p0[16]; ld16(p0, g_p0 + dst * 16);
            #pragma unroll
            for (int k = 0; k < 8; ++k) p0p[k] = pk(p0[2 * k], p0[2 * k + 1]);
        }
        float p1[24]; ld24(p1, g_p1 + dst * 24);
        ull rp[4];
        #pragma unroll
        for (int k = 0; k < 4; ++k) {
            float r0 = p1[6 * k] * sh.y + p1[6 * k + 1] * sh.z + p1[6 * k + 2] * sh.w;
            float r1 = p1[6 * k + 3] * sh.y + p1[6 * k + 4] * sh.z + p1[6 * k + 5] * sh.w;
            rp[k] = pk(r0, r1);
        }
        float s0 = score_pass(g_Mk + i0 * 576, x0, p0p, rp, dd, x1s, p1, sh.x);
        float s1 = score_pass(g_Mk + (i0 + 1) * 576, x0, p0p, rp, dd, x1s, p1, sh.x);
        float score = (s0 + f * (s1 - s0)) * 0.0028527222f;  // 1/(4*sqrt(24)*sqrt(320))
        float tc = 10.0f * (1.0f - d * 0.125f);
        float cut = (tc > 0.f) ? __expf(-__frcp_rn(tc)) : 0.f;
        ev = cut * __expf(score);
    }
    atomicAdd(&g_z[dst], ev);
    float fs = sqrtf(ev) * 0.0510310363f;  // sqrt(ev)/(4*sqrt(24))

    // ---- value phase
    ull o0p[8];
    float o1[24];
    #pragma unroll
    for (int k = 0; k < 8; ++k) o0p[k] = pk2(0.f);
    #pragma unroll
    for (int k = 0; k < 24; ++k) o1[k] = 0.f;

    value_pass(g_Mv + i0 * 576, x0, dd, x1s, sh, o0p, o1);
    float omf = 1.0f - f;
    ull omfp = pk2(omf);
    #pragma unroll
    for (int k = 0; k < 8; ++k) o0p[k] = f2mul(o0p[k], omfp);
    #pragma unroll
    for (int k = 0; k < 24; ++k) o1[k] *= omf;
    #pragma unroll
    for (int u = 0; u < 16; ++u) x0[u] *= f;
    #pragma unroll
    for (int u = 0; u < 8; ++u) dd[u] *= f;
    #pragma unroll
    for (int k = 0; k < 24; ++k) x1s[k] *= f;
    value_pass(g_Mv + (i0 + 1) * 576, x0, dd, x1s, sh, o0p, o1);

    // ---- vectorized scatter: 10 x red.v4 instead of 40 scalar atomics
    float* ob = out + dst * 40;
    float o0[16];
    #pragma unroll
    for (int k = 0; k < 8; ++k) {
        float2 q = upk(o0p[k]);
        o0[2 * k] = q.x * fs;
        o0[2 * k + 1] = q.y * fs;
    }
    #pragma unroll
    for (int k = 0; k < 4; ++k)
        red4(ob + 4 * k, o0[4 * k], o0[4 * k + 1], o0[4 * k + 2], o0[4 * k + 3]);
    #pragma unroll
    for (int k = 0; k < 6; ++k)
        red4(ob + 16 + 4 * k, o1[4 * k] * fs, o1[4 * k + 1] * fs,
             o1[4 * k + 2] * fs, o1[4 * k + 3] * fs);
}

// -------- epilogue: out[i] *= rsqrt(z[i])
__global__ void normalize(float* __restrict__ out, int n) {
    int i = blockIdx.x * 128 + threadIdx.x;
    if (i >= n) return;
    float zz = g_z[i];
    if (zz <= 0.f) zz = 1.f;
    float s = rsqrtf(zz);
    float4* o4 = reinterpret_cast<float4*>(out + i * 40);
    #pragma unroll
    for (int m = 0; m < 10; ++m) {
        float4 v = o4[m];
        v.x *= s; v.y *= s; v.z *= s; v.w *= s;
        o4[m] = v;
    }
}

extern "C" void kernel_launch(void* const* d_in, const int* in_sizes, int n_in,
                              void* d_out, int out_size) {
    const float* x   = (const float*)d_in[0];
    const int*   ei  = (const int*)d_in[1];
    const float* ea  = (const float*)d_in[2];
    const float* amf = (const float*)d_in[5];
    const float* Wq0 = (const float*)d_in[6];
    const float* Wq1 = (const float*)d_in[7];
    const float* Wk1 = (const float*)d_in[8];
    const float* Wk2 = (const float*)d_in[9];
    const float* Wv1 = (const float*)d_in[10];
    const float* Wv2 = (const float*)d_in[11];
    const float* Wd0 = (const float*)d_in[12];
    const float* Wd1 = (const float*)d_in[13];
    float* out = (float*)d_out;

    int n = in_sizes[0] / 40;
    int E = in_sizes[2] / 4;

    build_h<<<(TBLM + 1 + 255) / 256, 256>>>(Wk1, Wv1);
    hist_kernel<<<(E + 255) / 256, 256>>>(amf, E);
    scan_kernel<<<1, 1024>>>(TBLM);
    int nbScat = (E + 255) / 256;
    int nbNode = (n + 255) / 256;
    int nbM = ((TBLM + 1) * 288 + 255) / 256;
    mega_kernel<<<nbScat + nbNode + nbM, 256>>>(
        x, ei, ea, amf, Wq0, Wq1, Wd0, Wd1, Wk2, Wv2, out, n, E, nbScat, nbNode);
    edge_fused<<<(E + 127) / 128, 128>>>(x, out, E);
    normalize<<<(n + 127) / 128, 128>>>(out, n);
}

// round 14
// speedup vs baseline: 2.0866x; 1.0950x over previous
#include <cuda_runtime.h>
#include <math.h>

#define NMAX 10000
#define EMAX 160000
#define TBLM 2048
typedef unsigned long long ull;

// device scratch (no runtime allocation)
__device__ __align__(16) float g_p0[NMAX * 16];
__device__ __align__(16) float g_p1[NMAX * 24];
__device__ float g_z[NMAX];
__device__ __align__(16) float g_hk[(TBLM + 1) * 16];
__device__ __align__(16) float g_hv[(TBLM + 1) * 16];
__device__ __align__(16) float g_Mk[(TBLM + 1) * 576];  // M(d)[j] = hk(d) . Wk2col_j
__device__ __align__(16) float g_Mv[(TBLM + 1) * 576];
// edge sort (by d-bin) scratch; g_cnt zero-init at load, re-zeroed by normalize each launch
__device__ int g_cnt[TBLM];
__device__ int g_off[TBLM];
__device__ int g_src[EMAX];
__device__ int g_dst[EMAX];
__device__ __align__(16) float4 g_sea[EMAX];
__device__ float g_sd[EMAX];

// ---------- packed f32x2 primitives ----------
__device__ __forceinline__ ull pk2(float a) {
    ull r; asm("mov.b64 %0, {%1,%1};" : "=l"(r) : "f"(a)); return r;
}
__device__ __forceinline__ ull pk(float a, float b) {
    ull r; asm("mov.b64 %0, {%1,%2};" : "=l"(r) : "f"(a), "f"(b)); return r;
}
__device__ __forceinline__ float2 upk(ull a) {
    float2 f; asm("mov.b64 {%0,%1}, %2;" : "=f"(f.x), "=f"(f.y) : "l"(a)); return f;
}
__device__ __forceinline__ ull f2fma(ull a, ull b, ull c) {
    ull d; asm("fma.rn.f32x2 %0, %1, %2, %3;" : "=l"(d) : "l"(a), "l"(b), "l"(c)); return d;
}
__device__ __forceinline__ ull f2mul(ull a, ull b) {
    ull d; asm("mul.rn.f32x2 %0, %1, %2;" : "=l"(d) : "l"(a), "l"(b)); return d;
}
// vector reduction atomic: out[0..3] += {a,b,c,d} (16B-aligned)
__device__ __forceinline__ void red4(float* p, float a, float b, float c, float d) {
    asm volatile("red.global.add.v4.f32 [%0], {%1,%2,%3,%4};"
                 :: "l"(p), "f"(a), "f"(b), "f"(c), "f"(d) : "memory");
}

__device__ __forceinline__ void ld16(float o[16], const float* __restrict__ p) {
    const float4* p4 = reinterpret_cast<const float4*>(p);
    float4 t0 = p4[0], t1 = p4[1], t2 = p4[2], t3 = p4[3];
    o[0] = t0.x; o[1] = t0.y; o[2] = t0.z; o[3] = t0.w;
    o[4] = t1.x; o[5] = t1.y; o[6] = t1.z; o[7] = t1.w;
    o[8] = t2.x; o[9] = t2.y; o[10] = t2.z; o[11] = t2.w;
    o[12] = t3.x; o[13] = t3.y; o[14] = t3.z; o[15] = t3.w;
}
__device__ __forceinline__ void ld24(float o[24], const float* __restrict__ p) {
    const float4* p4 = reinterpret_cast<const float4*>(p);
    #pragma unroll
    for (int k = 0; k < 6; ++k) {
        float4 t = p4[k];
        o[4 * k] = t.x; o[4 * k + 1] = t.y; o[4 * k + 2] = t.z; o[4 * k + 3] = t.w;
    }
}

// -------- stage 1: radial h rows + edge d-bin histogram (g_cnt pre-zeroed)
__global__ void build_h_hist(const float* __restrict__ Wk1, const float* __restrict__ Wv1,
                             const float* __restrict__ amf, int E) {
    int i = blockIdx.x * 256 + threadIdx.x;
    // histogram part (covers all E edges)
    if (i < E) {
        int b = (int)(amf[i] * ((float)TBLM * 0.125f));
        if (b < 0) b = 0;
        if (b > TBLM - 1) b = TBLM - 1;
        atomicAdd(&g_cnt[b], 1);
    }
    // h table part
    if (i > TBLM) return;
    float d = (float)i * (8.0f / (float)TBLM);
    float emb[16];
    #pragma unroll
    for (int b = 0; b < 16; ++b) {
        float cb = 0.47058824f * (float)(b + 1);
        float diff = (d - cb) * 2.125f;
        float q = 1.0f - diff * diff;
        emb[b] = (q > 0.f) ? 33.7342930f * expf(-2.0f / q) : 0.f;
    }
    #pragma unroll
    for (int c = 0; c < 16; ++c) {
        float sk = 0.f, sv = 0.f;
        #pragma unroll
        for (int b = 0; b < 16; ++b) {
            sk = fmaf(emb[b], Wk1[b * 16 + c], sk);
            sv = fmaf(emb[b], Wv1[b * 16 + c], sv);
        }
        sk *= 0.25f; sv *= 0.25f;
        g_hk[i * 16 + c] = sk / (1.f + expf(-sk));
        g_hv[i * 16 + c] = sv / (1.f + expf(-sv));
    }
}

// -------- stage 2: exclusive scan of bins
__global__ __launch_bounds__(1024) void scan_kernel(int n) {
    __shared__ int part[1024];
    int t = threadIdx.x;
    int chunk = (n + 1023) / 1024;
    int base = t * chunk;
    int s = 0;
    for (int i = 0; i < chunk; ++i) {
        int j = base + i;
        if (j < n) s += g_cnt[j];
    }
    part[t] = s;
    __syncthreads();
    for (int off = 1; off < 1024; off <<= 1) {
        int v = (t >= off) ? part[t - off] : 0;
        __syncthreads();
        part[t] += v;
        __syncthreads();
    }
    int run = (t > 0) ? part[t - 1] : 0;
    for (int i = 0; i < chunk; ++i) {
        int j = base + i;
        if (j < n) {
            int c = g_cnt[j];
            g_off[j] = run;
            run += c;
        }
    }
}

// -------- stage 3 (mega): scatter + node_prep + build_M by block role
__global__ __launch_bounds__(256) void mega_kernel(
    const float* __restrict__ x, const int* __restrict__ ei,
    const float* __restrict__ ea, const float* __restrict__ amf,
    const float* __restrict__ Wq0, const float* __restrict__ Wq1,
    const float* __restrict__ Wd0, const float* __restrict__ Wd1,
    const float* __restrict__ Wk2, const float* __restrict__ Wv2,
    float* __restrict__ out, int n, int E, int nbScat, int nbNode) {
    int b = blockIdx.x;
    int t = threadIdx.x;
    if (b < nbScat) {
        // ---- scatter (edge reorder by d-bin)
        int e = b * 256 + t;
        if (e >= E) return;
        float d = amf[e];
        int bin = (int)(d * ((float)TBLM * 0.125f));
        if (bin < 0) bin = 0;
        if (bin > TBLM - 1) bin = TBLM - 1;
        int pos = atomicAdd(&g_off[bin], 1);
        g_src[pos] = ei[e];
        g_dst[pos] = ei[E + e];
        g_sea[pos] = reinterpret_cast<const float4*>(ea)[e];
        g_sd[pos] = d;
        return;
    }
    if (b < nbScat + nbNode) {
        // ---- node_prep
        __shared__ float C0[256];
        __shared__ float C1[64];
        {
            int u = t >> 4, v = t & 15;
            float s = 0.f;
            #pragma unroll
            for (int w = 0; w < 16; ++w) s = fmaf(Wq0[u * 16 + w], Wd0[w * 16 + v], s);
            C0[t] = s * 0.25f;
        }
        if (t < 64) {
            int u = t >> 3, v = t & 7;
            float s = 0.f;
            #pragma unroll
            for (int w = 0; w < 8; ++w) s = fmaf(Wq1[u * 8 + w], Wd1[w * 8 + v], s);
            C1[t] = s * 0.2041241452f;  // 1/(sqrt(8)*sqrt(3))
        }
        __syncthreads();
        int i = (b - nbScat) * 256 + t;
        if (i >= n) return;
        float x0[16];
        #pragma unroll
        for (int u = 0; u < 16; ++u) x0[u] = x[i * 40 + u];
        #pragma unroll
        for (int v = 0; v < 16; ++v) {
            float s = 0.f;
            #pragma unroll
            for (int u = 0; u < 16; ++u) s = fmaf(x0[u], C0[u * 16 + v], s);
            g_p0[i * 16 + v] = s;
        }
        float x1[24];
        #pragma unroll
        for (int k = 0; k < 24; ++k) x1[k] = x[i * 40 + 16 + k];
        #pragma unroll
        for (int v = 0; v < 8; ++v) {
            #pragma unroll
            for (int c = 0; c < 3; ++c) {
                float s = 0.f;
                #pragma unroll
                for (int u = 0; u < 8; ++u) s = fmaf(x1[u * 3 + c], C1[u * 8 + v], s);
                g_p1[i * 24 + v * 3 + c] = s;
            }
        }
        g_z[i] = 0.f;
        float4 z4 = make_float4(0.f, 0.f, 0.f, 0.f);
        float4* o4 = reinterpret_cast<float4*>(out + i * 40);
        #pragma unroll
        for (int m = 0; m < 10; ++m) o4[m] = z4;
        return;
    }
    // ---- build_M: idx over (TBLM+1)*288 work items
    int idx = (b - nbScat - nbNode) * 256 + t;
    int row = idx / 288;
    if (row > TBLM) return;
    int rem = idx % 288;
    int tbl = rem / 144;
    int j4 = (rem % 144) * 4;
    const float* h = (tbl ? g_hv : g_hk) + row * 16;
    const float* W = tbl ? Wv2 : Wk2;
    float a0 = 0.f, a1 = 0.f, a2 = 0.f, a3 = 0.f;
    #pragma unroll
    for (int c = 0; c < 16; ++c) {
        float hc = h[c];
        const float4 w = *reinterpret_cast<const float4*>(W + c * 576 + j4);
        a0 = fmaf(hc, w.x, a0); a1 = fmaf(hc, w.y, a1);
        a2 = fmaf(hc, w.z, a2); a3 = fmaf(hc, w.w, a3);
    }
    float* dst = (tbl ? g_Mv : g_Mk) + row * 576 + j4;
    *reinterpret_cast<float4*>(dst) = make_float4(a0, a1, a2, a3);
}

// -------- score pass over one M row
__device__ __forceinline__ float score_pass(
    const float* __restrict__ M, const float x0[16], const ull p0p[8],
    const ull rp[4], const float dd[8], const float x1s[24],
    const float p1[24], float sh0) {
    const ulonglong2* M2 = reinterpret_cast<const ulonglong2*>(M);
    ull acc = pk2(0.f);
    // B1: j=u*16+w, score += (x0u*sh0) * (p0 . Mrow_u)
    #pragma unroll
    for (int u = 0; u < 16; ++u) {
        ulonglong2 c0 = M2[u * 4], c1 = M2[u * 4 + 1], c2 = M2[u * 4 + 2], c3 = M2[u * 4 + 3];
        ull t = f2mul(p0p[0], c0.x);
        t = f2fma(p0p[1], c0.y, t); t = f2fma(p0p[2], c1.x, t); t = f2fma(p0p[3], c1.y, t);
        t = f2fma(p0p[4], c2.x, t); t = f2fma(p0p[5], c2.y, t);
        t = f2fma(p0p[6], c3.x, t); t = f2fma(p0p[7], c3.y, t);
        acc = f2fma(pk2(x0[u] * sh0), t, acc);
    }
    // B2: j=256+u*8+w, score += x0u * (r . Mrow_u)
    #pragma unroll
    for (int u = 0; u < 16; ++u) {
        ulonglong2 c0 = M2[64 + u * 2], c1 = M2[64 + u * 2 + 1];
        ull t = f2mul(rp[0], c0.x);
        t = f2fma(rp[1], c0.y, t); t = f2fma(rp[2], c1.x, t); t = f2fma(rp[3], c1.y, t);
        acc = f2fma(pk2(x0[u]), t, acc);
    }
    // B4: j=448+u*16+w, score += dd_u * (p0 . Mrow_u)
    #pragma unroll
    for (int u = 0; u < 8; ++u) {
        ulonglong2 c0 = M2[112 + u * 4], c1 = M2[112 + u * 4 + 1],
                   c2 = M2[112 + u * 4 + 2], c3 = M2[112 + u * 4 + 3];
        ull t = f2mul(p0p[0], c0.x);
        t = f2fma(p0p[1], c0.y, t); t = f2fma(p0p[2], c1.x, t); t = f2fma(p0p[3], c1.y, t);
        t = f2fma(p0p[4], c2.x, t); t = f2fma(p0p[5], c2.y, t);
        t = f2fma(p0p[6], c3.x, t); t = f2fma(p0p[7], c3.y, t);
        acc = f2fma(pk2(dd[u]), t, acc);
    }
    // B3: j=384+u*8+w, score += sum_u x1s_u . (sum_w M3[u][w] p1_w)
    float s3 = 0.f;
    #pragma unroll
    for (int u = 0; u < 8; ++u) {
        const float4* m4 = reinterpret_cast<const float4*>(M + 384 + u * 8);
        float4 A = m4[0], B = m4[1];
        float tvx = A.x * p1[0] + A.y * p1[3] + A.z * p1[6] + A.w * p1[9]
                  + B.x * p1[12] + B.y * p1[15] + B.z * p1[18] + B.w * p1[21];
        float tvy = A.x * p1[1] + A.y * p1[4] + A.z * p1[7] + A.w * p1[10]
                  + B.x * p1[13] + B.y * p1[16] + B.z * p1[19] + B.w * p1[22];
        float tvz = A.x * p1[2] + A.y * p1[5] + A.z * p1[8] + A.w * p1[11]
                  + B.x * p1[14] + B.y * p1[17] + B.z * p1[20] + B.w * p1[23];
        s3 += x1s[3 * u] * tvx + x1s[3 * u + 1] * tvy + x1s[3 * u + 2] * tvz;
    }
    float2 a2 = upk(acc);
    return a2.x + a2.y + s3;
}

// -------- value pass over one M row: accumulate o0 (packed) and o1 (scalar)
__device__ __forceinline__ void value_pass(
    const float* __restrict__ M, const float x0[16], const float dd[8],
    const float x1s[24], float4 sh, ull o0p[8], float o1[24]) {
    const ulonglong2* M2 = reinterpret_cast<const ulonglong2*>(M);
    // B1: o0[w] += (x0u*sh0) * M1[u][w]
    #pragma unroll
    for (int u = 0; u < 16; ++u) {
        ull fa = pk2(x0[u] * sh.x);
        ulonglong2 c0 = M2[u * 4], c1 = M2[u * 4 + 1], c2 = M2[u * 4 + 2], c3 = M2[u * 4 + 3];
        o0p[0] = f2fma(fa, c0.x, o0p[0]); o0p[1] = f2fma(fa, c0.y, o0p[1]);
        o0p[2] = f2fma(fa, c1.x, o0p[2]); o0p[3] = f2fma(fa, c1.y, o0p[3]);
        o0p[4] = f2fma(fa, c2.x, o0p[4]); o0p[5] = f2fma(fa, c2.y, o0p[5]);
        o0p[6] = f2fma(fa, c3.x, o0p[6]); o0p[7] = f2fma(fa, c3.y, o0p[7]);
    }
    // B4: o0[w] += dd_u * M4[u][w]
    #pragma unroll
    for (int u = 0; u < 8; ++u) {
        ull fa = pk2(dd[u]);
        ulonglong2 c0 = M2[112 + u * 4], c1 = M2[112 + u * 4 + 1],
                   c2 = M2[112 + u * 4 + 2], c3 = M2[112 + u * 4 + 3];
        o0p[0] = f2fma(fa, c0.x, o0p[0]); o0p[1] = f2fma(fa, c0.y, o0p[1]);
        o0p[2] = f2fma(fa, c1.x, o0p[2]); o0p[3] = f2fma(fa, c1.y, o0p[3]);
        o0p[4] = f2fma(fa, c2.x, o0p[4]); o0p[5] = f2fma(fa, c2.y, o0p[5]);
        o0p[6] = f2fma(fa, c3.x, o0p[6]); o0p[7] = f2fma(fa, c3.y, o0p[7]);
    }
    // B2: A[w] = sum_u x0u M2[u][w]
    ull Ap[4] = {pk2(0.f), pk2(0.f), pk2(0.f), pk2(0.f)};
    #pragma unroll
    for (int u = 0; u < 16; ++u) {
        ull fa = pk2(x0[u]);
        ulonglong2 c0 = M2[64 + u * 2], c1 = M2[64 + u * 2 + 1];
        Ap[0] = f2fma(fa, c0.x, Ap[0]); Ap[1] = f2fma(fa, c0.y, Ap[1]);
        Ap[2] = f2fma(fa, c1.x, Ap[2]); Ap[3] = f2fma(fa, c1.y, Ap[3]);
    }
    // B3: o1[w,:] += M3[u][w] * x1s[u,:]
    #pragma unroll
    for (int u = 0; u < 8; ++u) {
        const float4* m4 = reinterpret_cast<const float4*>(M + 384 + u * 8);
        float4 A = m4[0], B = m4[1];
        float xa = x1s[3 * u], xb = x1s[3 * u + 1], xc = x1s[3 * u + 2];
        o1[0] = fmaf(A.x, xa, o1[0]);  o1[1] = fmaf(A.x, xb, o1[1]);  o1[2] = fmaf(A.x, xc, o1[2]);
        o1[3] = fmaf(A.y, xa, o1[3]);  o1[4] = fmaf(A.y, xb, o1[4]);  o1[5] = fmaf(A.y, xc, o1[5]);
        o1[6] = fmaf(A.z, xa, o1[6]);  o1[7] = fmaf(A.z, xb, o1[7]);  o1[8] = fmaf(A.z, xc, o1[8]);
        o1[9] = fmaf(A.w, xa, o1[9]);  o1[10] = fmaf(A.w, xb, o1[10]); o1[11] = fmaf(A.w, xc, o1[11]);
        o1[12] = fmaf(B.x, xa, o1[12]); o1[13] = fmaf(B.x, xb, o1[13]); o1[14] = fmaf(B.x, xc, o1[14]);
        o1[15] = fmaf(B.y, xa, o1[15]); o1[16] = fmaf(B.y, xb, o1[16]); o1[17] = fmaf(B.y, xc, o1[17]);
        o1[18] = fmaf(B.z, xa, o1[18]); o1[19] = fmaf(B.z, xb, o1[19]); o1[20] = fmaf(B.z, xc, o1[20]);
        o1[21] = fmaf(B.w, xa, o1[21]); o1[22] = fmaf(B.w, xb, o1[22]); o1[23] = fmaf(B.w, xc, o1[23]);
    }
    // A-term: o1[w,:] += A[w] * sh1
    #pragma unroll
    for (int k = 0; k < 4; ++k) {
        float2 a2 = upk(Ap[k]);
        int w0 = 2 * k, w1 = 2 * k + 1;
        o1[3 * w0] = fmaf(a2.x, sh.y, o1[3 * w0]);
        o1[3 * w0 + 1] = fmaf(a2.x, sh.z, o1[3 * w0 + 1]);
        o1[3 * w0 + 2] = fmaf(a2.x, sh.w, o1[3 * w0 + 2]);
        o1[3 * w1] = fmaf(a2.y, sh.y, o1[3 * w1]);
        o1[3 * w1 + 1] = fmaf(a2.y, sh.z, o1[3 * w1 + 1]);
        o1[3 * w1 + 2] = fmaf(a2.y, sh.w, o1[3 * w1 + 2]);
    }
}

// -------- fused edge kernel: score + value, one edge/thread (d-sorted)
__global__ __launch_bounds__(128) void edge_fused(
    const float* __restrict__ x, float* __restrict__ out, int E) {
    int e = blockIdx.x * 128 + threadIdx.x;
    if (e >= E) return;
    int src = g_src[e], dst = g_dst[e];
    float4 sh = g_sea[e];
    float d = g_sd[e];

    // shared per-edge gathers
    float x0[16]; ld16(x0, x + src * 40);
    float x1s[24], dd[8];
    {
        float t[24]; ld24(t, x + src * 40 + 16);
        #pragma unroll
        for (int u = 0; u < 8; ++u) {
            dd[u] = (t[3 * u] * sh.y + t[3 * u + 1] * sh.z + t[3 * u + 2] * sh.w) * 0.57735027f;
            x1s[3 * u] = t[3 * u] * sh.x;
            x1s[3 * u + 1] = t[3 * u + 1] * sh.x;
            x1s[3 * u + 2] = t[3 * u + 2] * sh.x;
        }
    }
    float uu = d * ((float)TBLM * 0.125f);
    int i0 = (int)uu;
    if (i0 < 0) i0 = 0;
    if (i0 > TBLM - 1) i0 = TBLM - 1;
    float f = uu - (float)i0;

    // ---- score phase (p0/p1/rp live only here)
    float ev;
    {
        ull p0p[8];
        {
            float p0[16]; ld16(p0, g_p0 + dst * 16);
            #pragma unroll
            for (int k = 0; k < 8; ++k) p0p[k] = pk(p0[2 * k], p0[2 * k + 1]);
        }
        float p1[24]; ld24(p1, g_p1 + dst * 24);
        ull rp[4];
        #pragma unroll
        for (int k = 0; k < 4; ++k) {
            float r0 = p1[6 * k] * sh.y + p1[6 * k + 1] * sh.z + p1[6 * k + 2] * sh.w;
            float r1 = p1[6 * k + 3] * sh.y + p1[6 * k + 4] * sh.z + p1[6 * k + 5] * sh.w;
            rp[k] = pk(r0, r1);
        }
        float s0 = score_pass(g_Mk + i0 * 576, x0, p0p, rp, dd, x1s, p1, sh.x);
        float s1 = score_pass(g_Mk + (i0 + 1) * 576, x0, p0p, rp, dd, x1s, p1, sh.x);
        float score = (s0 + f * (s1 - s0)) * 0.0028527222f;  // 1/(4*sqrt(24)*sqrt(320))
        float tc = 10.0f * (1.0f - d * 0.125f);
        float cut = (tc > 0.f) ? __expf(-__frcp_rn(tc)) : 0.f;
        ev = cut * __expf(score);
    }
    atomicAdd(&g_z[dst], ev);
    float fs = sqrtf(ev) * 0.0510310363f;  // sqrt(ev)/(4*sqrt(24))

    // ---- value phase
    ull o0p[8];
    float o1[24];
    #pragma unroll
    for (int k = 0; k < 8; ++k) o0p[k] = pk2(0.f);
    #pragma unroll
    for (int k = 0; k < 24; ++k) o1[k] = 0.f;

    value_pass(g_Mv + i0 * 576, x0, dd, x1s, sh, o0p, o1);
    float omf = 1.0f - f;
    ull omfp = pk2(omf);
    #pragma unroll
    for (int k = 0; k < 8; ++k) o0p[k] = f2mul(o0p[k], omfp);
    #pragma unroll
    for (int k = 0; k < 24; ++k) o1[k] *= omf;
    #pragma unroll
    for (int u = 0; u < 16; ++u) x0[u] *= f;
    #pragma unroll
    for (int u = 0; u < 8; ++u) dd[u] *= f;
    #pragma unroll
    for (int k = 0; k < 24; ++k) x1s[k] *= f;
    value_pass(g_Mv + (i0 + 1) * 576, x0, dd, x1s, sh, o0p, o1);

    // ---- vectorized scatter: 10 x red.v4
    float* ob = out + dst * 40;
    float o0[16];
    #pragma unroll
    for (int k = 0; k < 8; ++k) {
        float2 q = upk(o0p[k]);
        o0[2 * k] = q.x * fs;
        o0[2 * k + 1] = q.y * fs;
    }
    #pragma unroll
    for (int k = 0; k < 4; ++k)
        red4(ob + 4 * k, o0[4 * k], o0[4 * k + 1], o0[4 * k + 2], o0[4 * k + 3]);
    #pragma unroll
    for (int k = 0; k < 6; ++k)
        red4(ob + 16 + 4 * k, o1[4 * k] * fs, o1[4 * k + 1] * fs,
             o1[4 * k + 2] * fs, o1[4 * k + 3] * fs);
}

// -------- epilogue: out[i] *= rsqrt(z[i]); re-zero g_cnt for next launch
__global__ void normalize(float* __restrict__ out, int n) {
    int i = blockIdx.x * 128 + threadIdx.x;
    if (i < TBLM) g_cnt[i] = 0;
    if (i >= n) return;
    float zz = g_z[i];
    if (zz <= 0.f) zz = 1.f;
    float s = rsqrtf(zz);
    float4* o4 = reinterpret_cast<float4*>(out + i * 40);
    #pragma unroll
    for (int m = 0; m < 10; ++m) {
        float4 v = o4[m];
        v.x *= s; v.y *= s; v.z *= s; v.w *= s;
        o4[m] = v;
    }
}

extern "C" void kernel_launch(void* const* d_in, const int* in_sizes, int n_in,
                              void* d_out, int out_size) {
    const float* x   = (const float*)d_in[0];
    const int*   ei  = (const int*)d_in[1];
    const float* ea  = (const float*)d_in[2];
    const float* amf = (const float*)d_in[5];
    const float* Wq0 = (const float*)d_in[6];
    const float* Wq1 = (const float*)d_in[7];
    const float* Wk1 = (const float*)d_in[8];
    const float* Wk2 = (const float*)d_in[9];
    const float* Wv1 = (const float*)d_in[10];
    const float* Wv2 = (const float*)d_in[11];
    const float* Wd0 = (const float*)d_in[12];
    const float* Wd1 = (const float*)d_in[13];
    float* out = (float*)d_out;

    int n = in_sizes[0] / 40;
    int E = in_sizes[2] / 4;

    build_h_hist<<<(E + 255) / 256, 256>>>(Wk1, Wv1, amf, E);
    scan_kernel<<<1, 1024>>>(TBLM);
    int nbScat = (E + 255) / 256;
    int nbNode = (n + 255) / 256;
    int nbM = ((TBLM + 1) * 288 + 255) / 256;
    mega_kernel<<<nbScat + nbNode + nbM, 256>>>(
        x, ei, ea, amf, Wq0, Wq1, Wd0, Wd1, Wk2, Wv2, out, n, E, nbScat, nbNode);
    edge_fused<<<(E + 127) / 128, 128>>>(x, out, E);
    normalize<<<(n + 127) / 128, 128>>>(out, n);
}

// round 15
// speedup vs baseline: 2.2711x; 1.0884x over previous
#include <cuda_runtime.h>
#include <math.h>

#define NMAX 10000
#define EMAX 160000
#define TBLM 2048
typedef unsigned long long ull;

// device scratch (no runtime allocation)
__device__ __align__(16) float g_p0[NMAX * 16];
__device__ __align__(16) float g_p1[NMAX * 24];
__device__ float g_z[NMAX];
__device__ __align__(16) float g_hk[(TBLM + 1) * 16];
__device__ __align__(16) float g_hv[(TBLM + 1) * 16];
__device__ __align__(16) float g_Mk[(TBLM + 1) * 576];  // M(d)[j] = hk(d) . Wk2col_j
__device__ __align__(16) float g_Mv[(TBLM + 1) * 576];
// edge sort (by d-bin) scratch; g_cnt zero-init at load, re-zeroed by normalize each launch
__device__ int g_cnt[TBLM];
__device__ int g_off[TBLM];
__device__ int g_src[EMAX];
__device__ int g_dst[EMAX];
__device__ __align__(16) float4 g_sea[EMAX];
__device__ float g_sd[EMAX];

// ---------- packed f32x2 primitives ----------
__device__ __forceinline__ ull pk2(float a) {
    ull r; asm("mov.b64 %0, {%1,%1};" : "=l"(r) : "f"(a)); return r;
}
__device__ __forceinline__ ull pk(float a, float b) {
    ull r; asm("mov.b64 %0, {%1,%2};" : "=l"(r) : "f"(a), "f"(b)); return r;
}
__device__ __forceinline__ float2 upk(ull a) {
    float2 f; asm("mov.b64 {%0,%1}, %2;" : "=f"(f.x), "=f"(f.y) : "l"(a)); return f;
}
__device__ __forceinline__ ull f2fma(ull a, ull b, ull c) {
    ull d; asm("fma.rn.f32x2 %0, %1, %2, %3;" : "=l"(d) : "l"(a), "l"(b), "l"(c)); return d;
}
__device__ __forceinline__ ull f2mul(ull a, ull b) {
    ull d; asm("mul.rn.f32x2 %0, %1, %2;" : "=l"(d) : "l"(a), "l"(b)); return d;
}
__device__ __forceinline__ ull f2add(ull a, ull b) {
    ull d; asm("add.rn.f32x2 %0, %1, %2;" : "=l"(d) : "l"(a), "l"(b)); return d;
}
// vector reduction atomic: out[0..3] += {a,b,c,d} (16B-aligned)
__device__ __forceinline__ void red4(float* p, float a, float b, float c, float d) {
    asm volatile("red.global.add.v4.f32 [%0], {%1,%2,%3,%4};"
                 :: "l"(p), "f"(a), "f"(b), "f"(c), "f"(d) : "memory");
}
// dot of 8 packed h with 4 ulonglong2 (16 floats)
__device__ __forceinline__ ull dot8c(const ull h[8], ulonglong2 c0, ulonglong2 c1,
                                     ulonglong2 c2, ulonglong2 c3) {
    ull s0 = f2mul(h[0], c0.x), s1 = f2mul(h[1], c0.y);
    s0 = f2fma(h[2], c1.x, s0); s1 = f2fma(h[3], c1.y, s1);
    s0 = f2fma(h[4], c2.x, s0); s1 = f2fma(h[5], c2.y, s1);
    s0 = f2fma(h[6], c3.x, s0); s1 = f2fma(h[7], c3.y, s1);
    return f2add(s0, s1);
}

__device__ __forceinline__ void ld16(float o[16], const float* __restrict__ p) {
    const float4* p4 = reinterpret_cast<const float4*>(p);
    float4 t0 = p4[0], t1 = p4[1], t2 = p4[2], t3 = p4[3];
    o[0] = t0.x; o[1] = t0.y; o[2] = t0.z; o[3] = t0.w;
    o[4] = t1.x; o[5] = t1.y; o[6] = t1.z; o[7] = t1.w;
    o[8] = t2.x; o[9] = t2.y; o[10] = t2.z; o[11] = t2.w;
    o[12] = t3.x; o[13] = t3.y; o[14] = t3.z; o[15] = t3.w;
}
__device__ __forceinline__ void ld24(float o[24], const float* __restrict__ p) {
    const float4* p4 = reinterpret_cast<const float4*>(p);
    #pragma unroll
    for (int k = 0; k < 6; ++k) {
        float4 t = p4[k];
        o[4 * k] = t.x; o[4 * k + 1] = t.y; o[4 * k + 2] = t.z; o[4 * k + 3] = t.w;
    }
}

// -------- stage 1: radial h rows + edge d-bin histogram (g_cnt pre-zeroed)
__global__ void build_h_hist(const float* __restrict__ Wk1, const float* __restrict__ Wv1,
                             const float* __restrict__ amf, int E) {
    int i = blockIdx.x * 256 + threadIdx.x;
    if (i < E) {
        int b = (int)(amf[i] * ((float)TBLM * 0.125f));
        if (b < 0) b = 0;
        if (b > TBLM - 1) b = TBLM - 1;
        atomicAdd(&g_cnt[b], 1);
    }
    if (i > TBLM) return;
    float d = (float)i * (8.0f / (float)TBLM);
    float emb[16];
    #pragma unroll
    for (int b = 0; b < 16; ++b) {
        float cb = 0.47058824f * (float)(b + 1);
        float diff = (d - cb) * 2.125f;
        float q = 1.0f - diff * diff;
        emb[b] = (q > 0.f) ? 33.7342930f * expf(-2.0f / q) : 0.f;
    }
    #pragma unroll
    for (int c = 0; c < 16; ++c) {
        float sk = 0.f, sv = 0.f;
        #pragma unroll
        for (int b = 0; b < 16; ++b) {
            sk = fmaf(emb[b], Wk1[b * 16 + c], sk);
            sv = fmaf(emb[b], Wv1[b * 16 + c], sv);
        }
        sk *= 0.25f; sv *= 0.25f;
        g_hk[i * 16 + c] = sk / (1.f + expf(-sk));
        g_hv[i * 16 + c] = sv / (1.f + expf(-sv));
    }
}

// -------- stage 2: exclusive scan of bins
__global__ __launch_bounds__(1024) void scan_kernel(int n) {
    __shared__ int part[1024];
    int t = threadIdx.x;
    int chunk = (n + 1023) / 1024;
    int base = t * chunk;
    int s = 0;
    for (int i = 0; i < chunk; ++i) {
        int j = base + i;
        if (j < n) s += g_cnt[j];
    }
    part[t] = s;
    __syncthreads();
    for (int off = 1; off < 1024; off <<= 1) {
        int v = (t >= off) ? part[t - off] : 0;
        __syncthreads();
        part[t] += v;
        __syncthreads();
    }
    int run = (t > 0) ? part[t - 1] : 0;
    for (int i = 0; i < chunk; ++i) {
        int j = base + i;
        if (j < n) {
            int c = g_cnt[j];
            g_off[j] = run;
            run += c;
        }
    }
}

// -------- stage 3 (mega): scatter + node_prep + build_M by block role
__global__ __launch_bounds__(256) void mega_kernel(
    const float* __restrict__ x, const int* __restrict__ ei,
    const float* __restrict__ ea, const float* __restrict__ amf,
    const float* __restrict__ Wq0, const float* __restrict__ Wq1,
    const float* __restrict__ Wd0, const float* __restrict__ Wd1,
    const float* __restrict__ Wk2, const float* __restrict__ Wv2,
    float* __restrict__ out, int n, int E, int nbScat, int nbNode) {
    int b = blockIdx.x;
    int t = threadIdx.x;
    if (b < nbScat) {
        int e = b * 256 + t;
        if (e >= E) return;
        float d = amf[e];
        int bin = (int)(d * ((float)TBLM * 0.125f));
        if (bin < 0) bin = 0;
        if (bin > TBLM - 1) bin = TBLM - 1;
        int pos = atomicAdd(&g_off[bin], 1);
        g_src[pos] = ei[e];
        g_dst[pos] = ei[E + e];
        g_sea[pos] = reinterpret_cast<const float4*>(ea)[e];
        g_sd[pos] = d;
        return;
    }
    if (b < nbScat + nbNode) {
        __shared__ float C0[256];
        __shared__ float C1[64];
        {
            int u = t >> 4, v = t & 15;
            float s = 0.f;
            #pragma unroll
            for (int w = 0; w < 16; ++w) s = fmaf(Wq0[u * 16 + w], Wd0[w * 16 + v], s);
            C0[t] = s * 0.25f;
        }
        if (t < 64) {
            int u = t >> 3, v = t & 7;
            float s = 0.f;
            #pragma unroll
            for (int w = 0; w < 8; ++w) s = fmaf(Wq1[u * 8 + w], Wd1[w * 8 + v], s);
            C1[t] = s * 0.2041241452f;  // 1/(sqrt(8)*sqrt(3))
        }
        __syncthreads();
        int i = (b - nbScat) * 256 + t;
        if (i >= n) return;
        float x0[16];
        #pragma unroll
        for (int u = 0; u < 16; ++u) x0[u] = x[i * 40 + u];
        #pragma unroll
        for (int v = 0; v < 16; ++v) {
            float s = 0.f;
            #pragma unroll
            for (int u = 0; u < 16; ++u) s = fmaf(x0[u], C0[u * 16 + v], s);
            g_p0[i * 16 + v] = s;
        }
        float x1[24];
        #pragma unroll
        for (int k = 0; k < 24; ++k) x1[k] = x[i * 40 + 16 + k];
        #pragma unroll
        for (int v = 0; v < 8; ++v) {
            #pragma unroll
            for (int c = 0; c < 3; ++c) {
                float s = 0.f;
                #pragma unroll
                for (int u = 0; u < 8; ++u) s = fmaf(x1[u * 3 + c], C1[u * 8 + v], s);
                g_p1[i * 24 + v * 3 + c] = s;
            }
        }
        g_z[i] = 0.f;
        float4 z4 = make_float4(0.f, 0.f, 0.f, 0.f);
        float4* o4 = reinterpret_cast<float4*>(out + i * 40);
        #pragma unroll
        for (int m = 0; m < 10; ++m) o4[m] = z4;
        return;
    }
    // ---- build_M
    int idx = (b - nbScat - nbNode) * 256 + t;
    int row = idx / 288;
    if (row > TBLM) return;
    int rem = idx % 288;
    int tbl = rem / 144;
    int j4 = (rem % 144) * 4;
    const float* h = (tbl ? g_hv : g_hk) + row * 16;
    const float* W = tbl ? Wv2 : Wk2;
    float a0 = 0.f, a1 = 0.f, a2 = 0.f, a3 = 0.f;
    #pragma unroll
    for (int c = 0; c < 16; ++c) {
        float hc = h[c];
        const float4 w = *reinterpret_cast<const float4*>(W + c * 576 + j4);
        a0 = fmaf(hc, w.x, a0); a1 = fmaf(hc, w.y, a1);
        a2 = fmaf(hc, w.z, a2); a3 = fmaf(hc, w.w, a3);
    }
    float* dst = (tbl ? g_Mv : g_Mk) + row * 576 + j4;
    *reinterpret_cast<float4*>(dst) = make_float4(a0, a1, a2, a3);
}

// -------- fused edge kernel: score + value, single-pass dual-row structure
__global__ __launch_bounds__(128) void edge_fused(
    const float* __restrict__ x, float* __restrict__ out, int E) {
    int e = blockIdx.x * 128 + threadIdx.x;
    if (e >= E) return;
    int src = g_src[e], dst = g_dst[e];
    float4 sh = g_sea[e];
    float d = g_sd[e];

    float x0[16]; ld16(x0, x + src * 40);
    float x1s[24], dd[8];
    {
        float t[24]; ld24(t, x + src * 40 + 16);
        #pragma unroll
        for (int u = 0; u < 8; ++u) {
            dd[u] = (t[3 * u] * sh.y + t[3 * u + 1] * sh.z + t[3 * u + 2] * sh.w) * 0.57735027f;
            x1s[3 * u] = t[3 * u] * sh.x;
            x1s[3 * u + 1] = t[3 * u + 1] * sh.x;
            x1s[3 * u + 2] = t[3 * u + 2] * sh.x;
        }
    }
    float uu = d * ((float)TBLM * 0.125f);
    int i0 = (int)uu;
    if (i0 < 0) i0 = 0;
    if (i0 > TBLM - 1) i0 = TBLM - 1;
    float f = uu - (float)i0;
    float omf = 1.0f - f;
    ull fp = pk2(f), omfp = pk2(omf);

    // ---- score: single pass over both rows, dual acc chains
    float ev;
    {
        ull p0p[8];
        {
            float p0[16]; ld16(p0, g_p0 + dst * 16);
            #pragma unroll
            for (int k = 0; k < 8; ++k) p0p[k] = pk(p0[2 * k], p0[2 * k + 1]);
        }
        float p1[24]; ld24(p1, g_p1 + dst * 24);
        ull rp[4];
        #pragma unroll
        for (int k = 0; k < 4; ++k) {
            float r0 = p1[6 * k] * sh.y + p1[6 * k + 1] * sh.z + p1[6 * k + 2] * sh.w;
            float r1 = p1[6 * k + 3] * sh.y + p1[6 * k + 4] * sh.z + p1[6 * k + 5] * sh.w;
            rp[k] = pk(r0, r1);
        }
        const ulonglong2* L = reinterpret_cast<const ulonglong2*>(g_Mk + i0 * 576);
        const ulonglong2* H = L + 144;
        ull aL = pk2(0.f), aH = pk2(0.f);
        // B1: g = x0u*sh0, dot p0
        #pragma unroll
        for (int u = 0; u < 16; ++u) {
            ulonglong2 l0 = L[u * 4], l1 = L[u * 4 + 1], l2 = L[u * 4 + 2], l3 = L[u * 4 + 3];
            ulonglong2 h0 = H[u * 4], h1 = H[u * 4 + 1], h2 = H[u * 4 + 2], h3 = H[u * 4 + 3];
            ull g = pk2(x0[u] * sh.x);
            aL = f2fma(g, dot8c(p0p, l0, l1, l2, l3), aL);
            aH = f2fma(g, dot8c(p0p, h0, h1, h2, h3), aH);
        }
        // B2: g = x0u, dot r (8 cols)
        #pragma unroll
        for (int u = 0; u < 16; ++u) {
            ulonglong2 l0 = L[64 + u * 2], l1 = L[64 + u * 2 + 1];
            ulonglong2 h0 = H[64 + u * 2], h1 = H[64 + u * 2 + 1];
            ull g = pk2(x0[u]);
            ull tL = f2mul(rp[0], l0.x);
            tL = f2fma(rp[1], l0.y, tL); tL = f2fma(rp[2], l1.x, tL); tL = f2fma(rp[3], l1.y, tL);
            ull tH = f2mul(rp[0], h0.x);
            tH = f2fma(rp[1], h0.y, tH); tH = f2fma(rp[2], h1.x, tH); tH = f2fma(rp[3], h1.y, tH);
            aL = f2fma(g, tL, aL); aH = f2fma(g, tH, aH);
        }
        // B4: g = dd[u], dot p0
        #pragma unroll
        for (int u = 0; u < 8; ++u) {
            ulonglong2 l0 = L[112 + u * 4], l1 = L[112 + u * 4 + 1],
                       l2 = L[112 + u * 4 + 2], l3 = L[112 + u * 4 + 3];
            ulonglong2 h0 = H[112 + u * 4], h1 = H[112 + u * 4 + 1],
                       h2 = H[112 + u * 4 + 2], h3 = H[112 + u * 4 + 3];
            ull g = pk2(dd[u]);
            aL = f2fma(g, dot8c(p0p, l0, l1, l2, l3), aL);
            aH = f2fma(g, dot8c(p0p, h0, h1, h2, h3), aH);
        }
        // B3: blend scalar rows, then triplet contraction
        float s3 = 0.f;
        const float4* mL = reinterpret_cast<const float4*>(g_Mk + i0 * 576 + 384);
        const float4* mH = mL + 144;
        #pragma unroll
        for (int u = 0; u < 8; ++u) {
            float4 AL = mL[u * 2], BL = mL[u * 2 + 1];
            float4 AH = mH[u * 2], BH = mH[u * 2 + 1];
            float m0 = fmaf(f, AH.x, omf * AL.x), m1 = fmaf(f, AH.y, omf * AL.y);
            float m2 = fmaf(f, AH.z, omf * AL.z), m3 = fmaf(f, AH.w, omf * AL.w);
            float m4 = fmaf(f, BH.x, omf * BL.x), m5 = fmaf(f, BH.y, omf * BL.y);
            float m6 = fmaf(f, BH.z, omf * BL.z), m7 = fmaf(f, BH.w, omf * BL.w);
            float tvx = m0 * p1[0] + m1 * p1[3] + m2 * p1[6] + m3 * p1[9]
                      + m4 * p1[12] + m5 * p1[15] + m6 * p1[18] + m7 * p1[21];
            float tvy = m0 * p1[1] + m1 * p1[4] + m2 * p1[7] + m3 * p1[10]
                      + m4 * p1[13] + m5 * p1[16] + m6 * p1[19] + m7 * p1[22];
            float tvz = m0 * p1[2] + m1 * p1[5] + m2 * p1[8] + m3 * p1[11]
                      + m4 * p1[14] + m5 * p1[17] + m6 * p1[20] + m7 * p1[23];
            s3 += x1s[3 * u] * tvx + x1s[3 * u + 1] * tvy + x1s[3 * u + 2] * tvz;
        }
        float2 a2L = upk(aL), a2H = upk(aH);
        float score = ((a2L.x + a2L.y) * omf + (a2H.x + a2H.y) * f + s3) * 0.0028527222f;
        float tc = 10.0f * (1.0f - d * 0.125f);
        float cut = (tc > 0.f) ? __expf(-__frcp_rn(tc)) : 0.f;
        ev = cut * __expf(score);
    }
    atomicAdd(&g_z[dst], ev);
    float fs = sqrtf(ev) * 0.0510310363f;  // sqrt(ev)/(4*sqrt(24))

    // ---- value: single pass, blend-on-load
    const ulonglong2* L = reinterpret_cast<const ulonglong2*>(g_Mv + i0 * 576);
    const ulonglong2* H = L + 144;
    ull o0p[8];
    #pragma unroll
    for (int k = 0; k < 8; ++k) o0p[k] = pk2(0.f);
    // B1: o0 += (x0u*sh0) * Mb
    #pragma unroll
    for (int u = 0; u < 16; ++u) {
        ulonglong2 l0 = L[u * 4], l1 = L[u * 4 + 1], l2 = L[u * 4 + 2], l3 = L[u * 4 + 3];
        ulonglong2 h0 = H[u * 4], h1 = H[u * 4 + 1], h2 = H[u * 4 + 2], h3 = H[u * 4 + 3];
        ull g = pk2(x0[u] * sh.x);
        o0p[0] = f2fma(g, f2fma(fp, h0.x, f2mul(omfp, l0.x)), o0p[0]);
        o0p[1] = f2fma(g, f2fma(fp, h0.y, f2mul(omfp, l0.y)), o0p[1]);
        o0p[2] = f2fma(g, f2fma(fp, h1.x, f2mul(omfp, l1.x)), o0p[2]);
        o0p[3] = f2fma(g, f2fma(fp, h1.y, f2mul(omfp, l1.y)), o0p[3]);
        o0p[4] = f2fma(g, f2fma(fp, h2.x, f2mul(omfp, l2.x)), o0p[4]);
        o0p[5] = f2fma(g, f2fma(fp, h2.y, f2mul(omfp, l2.y)), o0p[5]);
        o0p[6] = f2fma(g, f2fma(fp, h3.x, f2mul(omfp, l3.x)), o0p[6]);
        o0p[7] = f2fma(g, f2fma(fp, h3.y, f2mul(omfp, l3.y)), o0p[7]);
    }
    // B4: o0 += dd[u] * Mb
    #pragma unroll
    for (int u = 0; u < 8; ++u) {
        ulonglong2 l0 = L[112 + u * 4], l1 = L[112 + u * 4 + 1],
                   l2 = L[112 + u * 4 + 2], l3 = L[112 + u * 4 + 3];
        ulonglong2 h0 = H[112 + u * 4], h1 = H[112 + u * 4 + 1],
                   h2 = H[112 + u * 4 + 2], h3 = H[112 + u * 4 + 3];
        ull g = pk2(dd[u]);
        o0p[0] = f2fma(g, f2fma(fp, h0.x, f2mul(omfp, l0.x)), o0p[0]);
        o0p[1] = f2fma(g, f2fma(fp, h0.y, f2mul(omfp, l0.y)), o0p[1]);
        o0p[2] = f2fma(g, f2fma(fp, h1.x, f2mul(omfp, l1.x)), o0p[2]);
        o0p[3] = f2fma(g, f2fma(fp, h1.y, f2mul(omfp, l1.y)), o0p[3]);
        o0p[4] = f2fma(g, f2fma(fp, h2.x, f2mul(omfp, l2.x)), o0p[4]);
        o0p[5] = f2fma(g, f2fma(fp, h2.y, f2mul(omfp, l2.y)), o0p[5]);
        o0p[6] = f2fma(g, f2fma(fp, h3.x, f2mul(omfp, l3.x)), o0p[6]);
        o0p[7] = f2fma(g, f2fma(fp, h3.y, f2mul(omfp, l3.y)), o0p[7]);
    }
    // B2: A[w] = sum_u x0u * Mb
    ull Ap[4];
    #pragma unroll
    for (int k = 0; k < 4; ++k) Ap[k] = pk2(0.f);
    #pragma unroll
    for (int u = 0; u < 16; ++u) {
        ulonglong2 l0 = L[64 + u * 2], l1 = L[64 + u * 2 + 1];
        ulonglong2 h0 = H[64 + u * 2], h1 = H[64 + u * 2 + 1];
        ull g = pk2(x0[u]);
        Ap[0] = f2fma(g, f2fma(fp, h0.x, f2mul(omfp, l0.x)), Ap[0]);
        Ap[1] = f2fma(g, f2fma(fp, h0.y, f2mul(omfp, l0.y)), Ap[1]);
        Ap[2] = f2fma(g, f2fma(fp, h1.x, f2mul(omfp, l1.x)), Ap[2]);
        Ap[3] = f2fma(g, f2fma(fp, h1.y, f2mul(omfp, l1.y)), Ap[3]);
    }
    // B3: o1 += Mb[u][w] * x1s[u,:]
    float o1[24];
    #pragma unroll
    for (int k = 0; k < 24; ++k) o1[k] = 0.f;
    {
        const float4* mL = reinterpret_cast<const float4*>(g_Mv + i0 * 576 + 384);
        const float4* mH = mL + 144;
        #pragma unroll
        for (int u = 0; u < 8; ++u) {
            float4 AL = mL[u * 2], BL = mL[u * 2 + 1];
            float4 AH = mH[u * 2], BH = mH[u * 2 + 1];
            float m0 = fmaf(f, AH.x, omf * AL.x), m1 = fmaf(f, AH.y, omf * AL.y);
            float m2 = fmaf(f, AH.z, omf * AL.z), m3 = fmaf(f, AH.w, omf * AL.w);
            float m4 = fmaf(f, BH.x, omf * BL.x), m5 = fmaf(f, BH.y, omf * BL.y);
            float m6 = fmaf(f, BH.z, omf * BL.z), m7 = fmaf(f, BH.w, omf * BL.w);
            float xa = x1s[3 * u], xb = x1s[3 * u + 1], xc = x1s[3 * u + 2];
            o1[0] = fmaf(m0, xa, o1[0]);  o1[1] = fmaf(m0, xb, o1[1]);  o1[2] = fmaf(m0, xc, o1[2]);
            o1[3] = fmaf(m1, xa, o1[3]);  o1[4] = fmaf(m1, xb, o1[4]);  o1[5] = fmaf(m1, xc, o1[5]);
            o1[6] = fmaf(m2, xa, o1[6]);  o1[7] = fmaf(m2, xb, o1[7]);  o1[8] = fmaf(m2, xc, o1[8]);
            o1[9] = fmaf(m3, xa, o1[9]);  o1[10] = fmaf(m3, xb, o1[10]); o1[11] = fmaf(m3, xc, o1[11]);
            o1[12] = fmaf(m4, xa, o1[12]); o1[13] = fmaf(m4, xb, o1[13]); o1[14] = fmaf(m4, xc, o1[14]);
            o1[15] = fmaf(m5, xa, o1[15]); o1[16] = fmaf(m5, xb, o1[16]); o1[17] = fmaf(m5, xc, o1[17]);
            o1[18] = fmaf(m6, xa, o1[18]); o1[19] = fmaf(m6, xb, o1[19]); o1[20] = fmaf(m6, xc, o1[20]);
            o1[21] = fmaf(m7, xa, o1[21]); o1[22] = fmaf(m7, xb, o1[22]); o1[23] = fmaf(m7, xc, o1[23]);
        }
    }
    // A-term: o1[w,:] += A[w] * sh1
    #pragma unroll
    for (int k = 0; k < 4; ++k) {
        float2 a2 = upk(Ap[k]);
        int w0 = 2 * k, w1 = 2 * k + 1;
        o1[3 * w0] = fmaf(a2.x, sh.y, o1[3 * w0]);
        o1[3 * w0 + 1] = fmaf(a2.x, sh.z, o1[3 * w0 + 1]);
        o1[3 * w0 + 2] = fmaf(a2.x, sh.w, o1[3 * w0 + 2]);
        o1[3 * w1] = fmaf(a2.y, sh.y, o1[3 * w1]);
        o1[3 * w1 + 1] = fmaf(a2.y, sh.z, o1[3 * w1 + 1]);
        o1[3 * w1 + 2] = fmaf(a2.y, sh.w, o1[3 * w1 + 2]);
    }

    // ---- vectorized scatter: 10 x red.v4
    float* ob = out + dst * 40;
    float o0[16];
    #pragma unroll
    for (int k = 0; k < 8; ++k) {
        float2 q = upk(o0p[k]);
        o0[2 * k] = q.x * fs;
        o0[2 * k + 1] = q.y * fs;
    }
    #pragma unroll
    for (int k = 0; k < 4; ++k)
        red4(ob + 4 * k, o0[4 * k], o0[4 * k + 1], o0[4 * k + 2], o0[4 * k + 3]);
    #pragma unroll
    for (int k = 0; k < 6; ++k)
        red4(ob + 16 + 4 * k, o1[4 * k] * fs, o1[4 * k + 1] * fs,
             o1[4 * k + 2] * fs, o1[4 * k + 3] * fs);
}

// -------- epilogue: out[i] *= rsqrt(z[i]); re-zero g_cnt for next launch
__global__ void normalize(float* __restrict__ out, int n) {
    int i = blockIdx.x * 128 + threadIdx.x;
    if (i < TBLM) g_cnt[i] = 0;
    if (i >= n) return;
    float zz = g_z[i];
    if (zz <= 0.f) zz = 1.f;
    float s = rsqrtf(zz);
    float4* o4 = reinterpret_cast<float4*>(out + i * 40);
    #pragma unroll
    for (int m = 0; m < 10; ++m) {
        float4 v = o4[m];
        v.x *= s; v.y *= s; v.z *= s; v.w *= s;
        o4[m] = v;
    }
}

extern "C" void kernel_launch(void* const* d_in, const int* in_sizes, int n_in,
                              void* d_out, int out_size) {
    const float* x   = (const float*)d_in[0];
    const int*   ei  = (const int*)d_in[1];
    const float* ea  = (const float*)d_in[2];
    const float* amf = (const float*)d_in[5];
    const float* Wq0 = (const float*)d_in[6];
    const float* Wq1 = (const float*)d_in[7];
    const float* Wk1 = (const float*)d_in[8];
    const float* Wk2 = (const float*)d_in[9];
    const float* Wv1 = (const float*)d_in[10];
    const float* Wv2 = (const float*)d_in[11];
    const float* Wd0 = (const float*)d_in[12];
    const float* Wd1 = (const float*)d_in[13];
    float* out = (float*)d_out;

    int n = in_sizes[0] / 40;
    int E = in_sizes[2] / 4;

    build_h_hist<<<(E + 255) / 256, 256>>>(Wk1, Wv1, amf, E);
    scan_kernel<<<1, 1024>>>(TBLM);
    int nbScat = (E + 255) / 256;
    int nbNode = (n + 255) / 256;
    int nbM = ((TBLM + 1) * 288 + 255) / 256;
    mega_kernel<<<nbScat + nbNode + nbM, 256>>>(
        x, ei, ea, amf, Wq0, Wq1, Wd0, Wd1, Wk2, Wv2, out, n, E, nbScat, nbNode);
    edge_fused<<<(E + 127) / 128, 128>>>(x, out, E);
    normalize<<<(n + 127) / 128, 128>>>(out, n);
}

// round 16
// speedup vs baseline: 2.9592x; 1.3030x over previous
#include <cuda_runtime.h>
#include <math.h>

#define NMAX 10000
#define EMAX 160000
#define TBLM 2048
typedef unsigned long long ull;

// device scratch (no runtime allocation)
__device__ __align__(16) float g_p0[NMAX * 16];
__device__ __align__(16) float g_p1[NMAX * 24];
__device__ float g_z[NMAX];
__device__ __align__(16) float g_hk[(TBLM + 1) * 16];
__device__ __align__(16) float g_hv[(TBLM + 1) * 16];
__device__ __align__(16) float g_Mk[(TBLM + 1) * 576];  // M(d)[j] = hk(d) . Wk2col_j
__device__ __align__(16) float g_Mv[(TBLM + 1) * 576];
// edge sort (by d-bin) scratch; g_cnt zero-init at load, re-zeroed by normalize each launch
__device__ int g_cnt[TBLM];
__device__ int g_off[TBLM];
__device__ int g_start[TBLM];
__device__ int g_src[EMAX];
__device__ int g_dst[EMAX];
__device__ __align__(16) float4 g_sea[EMAX];
__device__ float g_sd[EMAX];

// ---------- packed f32x2 primitives ----------
__device__ __forceinline__ ull pk2(float a) {
    ull r; asm("mov.b64 %0, {%1,%1};" : "=l"(r) : "f"(a)); return r;
}
__device__ __forceinline__ ull pk(float a, float b) {
    ull r; asm("mov.b64 %0, {%1,%2};" : "=l"(r) : "f"(a), "f"(b)); return r;
}
__device__ __forceinline__ float2 upk(ull a) {
    float2 f; asm("mov.b64 {%0,%1}, %2;" : "=f"(f.x), "=f"(f.y) : "l"(a)); return f;
}
__device__ __forceinline__ ull f2fma(ull a, ull b, ull c) {
    ull d; asm("fma.rn.f32x2 %0, %1, %2, %3;" : "=l"(d) : "l"(a), "l"(b), "l"(c)); return d;
}
__device__ __forceinline__ ull f2mul(ull a, ull b) {
    ull d; asm("mul.rn.f32x2 %0, %1, %2;" : "=l"(d) : "l"(a), "l"(b)); return d;
}
__device__ __forceinline__ ull f2add(ull a, ull b) {
    ull d; asm("add.rn.f32x2 %0, %1, %2;" : "=l"(d) : "l"(a), "l"(b)); return d;
}
// vector reduction atomic: out[0..3] += {a,b,c,d} (16B-aligned)
__device__ __forceinline__ void red4(float* p, float a, float b, float c, float d) {
    asm volatile("red.global.add.v4.f32 [%0], {%1,%2,%3,%4};"
                 :: "l"(p), "f"(a), "f"(b), "f"(c), "f"(d) : "memory");
}
// dot of 8 packed h with 4 ulonglong2 (16 floats)
__device__ __forceinline__ ull dot8c(const ull h[8], ulonglong2 c0, ulonglong2 c1,
                                     ulonglong2 c2, ulonglong2 c3) {
    ull s0 = f2mul(h[0], c0.x), s1 = f2mul(h[1], c0.y);
    s0 = f2fma(h[2], c1.x, s0); s1 = f2fma(h[3], c1.y, s1);
    s0 = f2fma(h[4], c2.x, s0); s1 = f2fma(h[5], c2.y, s1);
    s0 = f2fma(h[6], c3.x, s0); s1 = f2fma(h[7], c3.y, s1);
    return f2add(s0, s1);
}

__device__ __forceinline__ void ld16(float o[16], const float* __restrict__ p) {
    const float4* p4 = reinterpret_cast<const float4*>(p);
    float4 t0 = p4[0], t1 = p4[1], t2 = p4[2], t3 = p4[3];
    o[0] = t0.x; o[1] = t0.y; o[2] = t0.z; o[3] = t0.w;
    o[4] = t1.x; o[5] = t1.y; o[6] = t1.z; o[7] = t1.w;
    o[8] = t2.x; o[9] = t2.y; o[10] = t2.z; o[11] = t2.w;
    o[12] = t3.x; o[13] = t3.y; o[14] = t3.z; o[15] = t3.w;
}
__device__ __forceinline__ void ld24(float o[24], const float* __restrict__ p) {
    const float4* p4 = reinterpret_cast<const float4*>(p);
    #pragma unroll
    for (int k = 0; k < 6; ++k) {
        float4 t = p4[k];
        o[4 * k] = t.x; o[4 * k + 1] = t.y; o[4 * k + 2] = t.z; o[4 * k + 3] = t.w;
    }
}

// -------- stage 1: radial h rows + edge d-bin histogram (g_cnt pre-zeroed)
__global__ void build_h_hist(const float* __restrict__ Wk1, const float* __restrict__ Wv1,
                             const float* __restrict__ amf, int E) {
    int i = blockIdx.x * 256 + threadIdx.x;
    if (i < E) {
        int b = (int)(amf[i] * ((float)TBLM * 0.125f));
        if (b < 0) b = 0;
        if (b > TBLM - 1) b = TBLM - 1;
        atomicAdd(&g_cnt[b], 1);
    }
    if (i > TBLM) return;
    float d = (float)i * (8.0f / (float)TBLM);
    float emb[16];
    #pragma unroll
    for (int b = 0; b < 16; ++b) {
        float cb = 0.47058824f * (float)(b + 1);
        float diff = (d - cb) * 2.125f;
        float q = 1.0f - diff * diff;
        emb[b] = (q > 0.f) ? 33.7342930f * expf(-2.0f / q) : 0.f;
    }
    #pragma unroll
    for (int c = 0; c < 16; ++c) {
        float sk = 0.f, sv = 0.f;
        #pragma unroll
        for (int b = 0; b < 16; ++b) {
            sk = fmaf(emb[b], Wk1[b * 16 + c], sk);
            sv = fmaf(emb[b], Wv1[b * 16 + c], sv);
        }
        sk *= 0.25f; sv *= 0.25f;
        g_hk[i * 16 + c] = sk / (1.f + expf(-sk));
        g_hv[i * 16 + c] = sv / (1.f + expf(-sv));
    }
}

// -------- stage 2: exclusive scan of bins (writes cursor g_off + stable g_start)
__global__ __launch_bounds__(1024) void scan_kernel(int n) {
    __shared__ int part[1024];
    int t = threadIdx.x;
    int chunk = (n + 1023) / 1024;
    int base = t * chunk;
    int s = 0;
    for (int i = 0; i < chunk; ++i) {
        int j = base + i;
        if (j < n) s += g_cnt[j];
    }
    part[t] = s;
    __syncthreads();
    for (int off = 1; off < 1024; off <<= 1) {
        int v = (t >= off) ? part[t - off] : 0;
        __syncthreads();
        part[t] += v;
        __syncthreads();
    }
    int run = (t > 0) ? part[t - 1] : 0;
    for (int i = 0; i < chunk; ++i) {
        int j = base + i;
        if (j < n) {
            int c = g_cnt[j];
            g_off[j] = run;
            g_start[j] = run;
            run += c;
        }
    }
}

// -------- stage 3 (mega): scatter + node_prep + build_M by block role
__global__ __launch_bounds__(256) void mega_kernel(
    const float* __restrict__ x, const int* __restrict__ ei,
    const float* __restrict__ ea, const float* __restrict__ amf,
    const float* __restrict__ Wq0, const float* __restrict__ Wq1,
    const float* __restrict__ Wd0, const float* __restrict__ Wd1,
    const float* __restrict__ Wk2, const float* __restrict__ Wv2,
    float* __restrict__ out, int n, int E, int nbScat, int nbNode) {
    int b = blockIdx.x;
    int t = threadIdx.x;
    if (b < nbScat) {
        int e = b * 256 + t;
        if (e >= E) return;
        float d = amf[e];
        int bin = (int)(d * ((float)TBLM * 0.125f));
        if (bin < 0) bin = 0;
        if (bin > TBLM - 1) bin = TBLM - 1;
        int pos = atomicAdd(&g_off[bin], 1);
        g_src[pos] = ei[e];
        g_dst[pos] = ei[E + e];
        g_sea[pos] = reinterpret_cast<const float4*>(ea)[e];
        g_sd[pos] = d;
        return;
    }
    if (b < nbScat + nbNode) {
        __shared__ float C0[256];
        __shared__ float C1[64];
        {
            int u = t >> 4, v = t & 15;
            float s = 0.f;
            #pragma unroll
            for (int w = 0; w < 16; ++w) s = fmaf(Wq0[u * 16 + w], Wd0[w * 16 + v], s);
            C0[t] = s * 0.25f;
        }
        if (t < 64) {
            int u = t >> 3, v = t & 7;
            float s = 0.f;
            #pragma unroll
            for (int w = 0; w < 8; ++w) s = fmaf(Wq1[u * 8 + w], Wd1[w * 8 + v], s);
            C1[t] = s * 0.2041241452f;  // 1/(sqrt(8)*sqrt(3))
        }
        __syncthreads();
        int i = (b - nbScat) * 256 + t;
        if (i >= n) return;
        float x0[16];
        #pragma unroll
        for (int u = 0; u < 16; ++u) x0[u] = x[i * 40 + u];
        #pragma unroll
        for (int v = 0; v < 16; ++v) {
            float s = 0.f;
            #pragma unroll
            for (int u = 0; u < 16; ++u) s = fmaf(x0[u], C0[u * 16 + v], s);
            g_p0[i * 16 + v] = s;
        }
        float x1[24];
        #pragma unroll
        for (int k = 0; k < 24; ++k) x1[k] = x[i * 40 + 16 + k];
        #pragma unroll
        for (int v = 0; v < 8; ++v) {
            #pragma unroll
            for (int c = 0; c < 3; ++c) {
                float s = 0.f;
                #pragma unroll
                for (int u = 0; u < 8; ++u) s = fmaf(x1[u * 3 + c], C1[u * 8 + v], s);
                g_p1[i * 24 + v * 3 + c] = s;
            }
        }
        g_z[i] = 0.f;
        float4 z4 = make_float4(0.f, 0.f, 0.f, 0.f);
        float4* o4 = reinterpret_cast<float4*>(out + i * 40);
        #pragma unroll
        for (int m = 0; m < 10; ++m) o4[m] = z4;
        return;
    }
    // ---- build_M
    int idx = (b - nbScat - nbNode) * 256 + t;
    int row = idx / 288;
    if (row > TBLM) return;
    int rem = idx % 288;
    int tbl = rem / 144;
    int j4 = (rem % 144) * 4;
    const float* h = (tbl ? g_hv : g_hk) + row * 16;
    const float* W = tbl ? Wv2 : Wk2;
    float a0 = 0.f, a1 = 0.f, a2 = 0.f, a3 = 0.f;
    #pragma unroll
    for (int c = 0; c < 16; ++c) {
        float hc = h[c];
        const float4 w = *reinterpret_cast<const float4*>(W + c * 576 + j4);
        a0 = fmaf(hc, w.x, a0); a1 = fmaf(hc, w.y, a1);
        a2 = fmaf(hc, w.z, a2); a3 = fmaf(hc, w.w, a3);
    }
    float* dst = (tbl ? g_Mv : g_Mk) + row * 576 + j4;
    *reinterpret_cast<float4*>(dst) = make_float4(a0, a1, a2, a3);
}

// -------- fused edge kernel: ONE BLOCK PER d-BIN; M rows staged in smem (broadcast reads)
__global__ __launch_bounds__(96) void edge_fused(
    const float* __restrict__ x, float* __restrict__ out, int E) {
    __shared__ __align__(16) float sM[2304];  // [Mk row b | Mk row b+1 | Mv row b | Mv row b+1]
    int b = blockIdx.x;
    int t = threadIdx.x;
    {
        float4* s4 = reinterpret_cast<float4*>(sM);
        const float4* mk4 = reinterpret_cast<const float4*>(g_Mk + b * 576);
        const float4* mv4 = reinterpret_cast<const float4*>(g_Mv + b * 576);
        for (int i = t; i < 288; i += 96) s4[i] = mk4[i];          // rows b, b+1 contiguous
        for (int i = t; i < 288; i += 96) s4[288 + i] = mv4[i];
    }
    int start = g_start[b];
    int end = (b + 1 < TBLM) ? g_start[b + 1] : E;
    __syncthreads();

    for (int e = start + t; e < end; e += 96) {
        int src = g_src[e], dst = g_dst[e];
        float4 sh = g_sea[e];
        float d = g_sd[e];

        float x0[16]; ld16(x0, x + src * 40);
        float x1s[24], dd[8];
        {
            float tt[24]; ld24(tt, x + src * 40 + 16);
            #pragma unroll
            for (int u = 0; u < 8; ++u) {
                dd[u] = (tt[3 * u] * sh.y + tt[3 * u + 1] * sh.z + tt[3 * u + 2] * sh.w) * 0.57735027f;
                x1s[3 * u] = tt[3 * u] * sh.x;
                x1s[3 * u + 1] = tt[3 * u + 1] * sh.x;
                x1s[3 * u + 2] = tt[3 * u + 2] * sh.x;
            }
        }
        float f = d * ((float)TBLM * 0.125f) - (float)b;
        if (f < 0.f) f = 0.f;
        if (f > 1.f) f = 1.f;
        float omf = 1.0f - f;
        ull fp = pk2(f), omfp = pk2(omf);

        // ---- score: dual acc chains over smem rows
        float ev;
        {
            ull p0p[8];
            {
                float p0[16]; ld16(p0, g_p0 + dst * 16);
                #pragma unroll
                for (int k = 0; k < 8; ++k) p0p[k] = pk(p0[2 * k], p0[2 * k + 1]);
            }
            float p1[24]; ld24(p1, g_p1 + dst * 24);
            ull rp[4];
            #pragma unroll
            for (int k = 0; k < 4; ++k) {
                float r0 = p1[6 * k] * sh.y + p1[6 * k + 1] * sh.z + p1[6 * k + 2] * sh.w;
                float r1 = p1[6 * k + 3] * sh.y + p1[6 * k + 4] * sh.z + p1[6 * k + 5] * sh.w;
                rp[k] = pk(r0, r1);
            }
            const ulonglong2* L = reinterpret_cast<const ulonglong2*>(sM);
            const ulonglong2* H = L + 144;
            ull aL = pk2(0.f), aH = pk2(0.f);
            #pragma unroll
            for (int u = 0; u < 16; ++u) {
                ull g = pk2(x0[u] * sh.x);
                aL = f2fma(g, dot8c(p0p, L[u * 4], L[u * 4 + 1], L[u * 4 + 2], L[u * 4 + 3]), aL);
                aH = f2fma(g, dot8c(p0p, H[u * 4], H[u * 4 + 1], H[u * 4 + 2], H[u * 4 + 3]), aH);
            }
            #pragma unroll
            for (int u = 0; u < 16; ++u) {
                ulonglong2 l0 = L[64 + u * 2], l1 = L[64 + u * 2 + 1];
                ulonglong2 h0 = H[64 + u * 2], h1 = H[64 + u * 2 + 1];
                ull g = pk2(x0[u]);
                ull tL = f2mul(rp[0], l0.x);
                tL = f2fma(rp[1], l0.y, tL); tL = f2fma(rp[2], l1.x, tL); tL = f2fma(rp[3], l1.y, tL);
                ull tH = f2mul(rp[0], h0.x);
                tH = f2fma(rp[1], h0.y, tH); tH = f2fma(rp[2], h1.x, tH); tH = f2fma(rp[3], h1.y, tH);
                aL = f2fma(g, tL, aL); aH = f2fma(g, tH, aH);
            }
            #pragma unroll
            for (int u = 0; u < 8; ++u) {
                ull g = pk2(dd[u]);
                aL = f2fma(g, dot8c(p0p, L[112 + u * 4], L[112 + u * 4 + 1],
                                    L[112 + u * 4 + 2], L[112 + u * 4 + 3]), aL);
                aH = f2fma(g, dot8c(p0p, H[112 + u * 4], H[112 + u * 4 + 1],
                                    H[112 + u * 4 + 2], H[112 + u * 4 + 3]), aH);
            }
            float s3 = 0.f;
            const float4* mL = reinterpret_cast<const float4*>(sM + 384);
            const float4* mH = mL + 144;
            #pragma unroll
            for (int u = 0; u < 8; ++u) {
                float4 AL = mL[u * 2], BL = mL[u * 2 + 1];
                float4 AH = mH[u * 2], BH = mH[u * 2 + 1];
                float m0 = fmaf(f, AH.x, omf * AL.x), m1 = fmaf(f, AH.y, omf * AL.y);
                float m2 = fmaf(f, AH.z, omf * AL.z), m3 = fmaf(f, AH.w, omf * AL.w);
                float m4 = fmaf(f, BH.x, omf * BL.x), m5 = fmaf(f, BH.y, omf * BL.y);
                float m6 = fmaf(f, BH.z, omf * BL.z), m7 = fmaf(f, BH.w, omf * BL.w);
                float tvx = m0 * p1[0] + m1 * p1[3] + m2 * p1[6] + m3 * p1[9]
                          + m4 * p1[12] + m5 * p1[15] + m6 * p1[18] + m7 * p1[21];
                float tvy = m0 * p1[1] + m1 * p1[4] + m2 * p1[7] + m3 * p1[10]
                          + m4 * p1[13] + m5 * p1[16] + m6 * p1[19] + m7 * p1[22];
                float tvz = m0 * p1[2] + m1 * p1[5] + m2 * p1[8] + m3 * p1[11]
                          + m4 * p1[14] + m5 * p1[17] + m6 * p1[20] + m7 * p1[23];
                s3 += x1s[3 * u] * tvx + x1s[3 * u + 1] * tvy + x1s[3 * u + 2] * tvz;
            }
            float2 a2L = upk(aL), a2H = upk(aH);
            float score = ((a2L.x + a2L.y) * omf + (a2H.x + a2H.y) * f + s3) * 0.0028527222f;
            float tc = 10.0f * (1.0f - d * 0.125f);
            float cut = (tc > 0.f) ? __expf(-__frcp_rn(tc)) : 0.f;
            ev = cut * __expf(score);
        }
        atomicAdd(&g_z[dst], ev);
        float fs = sqrtf(ev) * 0.0510310363f;  // sqrt(ev)/(4*sqrt(24))

        // ---- value: blend-on-load from smem
        const ulonglong2* L = reinterpret_cast<const ulonglong2*>(sM + 1152);
        const ulonglong2* H = L + 144;
        ull o0p[8];
        #pragma unroll
        for (int k = 0; k < 8; ++k) o0p[k] = pk2(0.f);
        #pragma unroll
        for (int u = 0; u < 16; ++u) {
            ulonglong2 l0 = L[u * 4], l1 = L[u * 4 + 1], l2 = L[u * 4 + 2], l3 = L[u * 4 + 3];
            ulonglong2 h0 = H[u * 4], h1 = H[u * 4 + 1], h2 = H[u * 4 + 2], h3 = H[u * 4 + 3];
            ull g = pk2(x0[u] * sh.x);
            o0p[0] = f2fma(g, f2fma(fp, h0.x, f2mul(omfp, l0.x)), o0p[0]);
            o0p[1] = f2fma(g, f2fma(fp, h0.y, f2mul(omfp, l0.y)), o0p[1]);
            o0p[2] = f2fma(g, f2fma(fp, h1.x, f2mul(omfp, l1.x)), o0p[2]);
            o0p[3] = f2fma(g, f2fma(fp, h1.y, f2mul(omfp, l1.y)), o0p[3]);
            o0p[4] = f2fma(g, f2fma(fp, h2.x, f2mul(omfp, l2.x)), o0p[4]);
            o0p[5] = f2fma(g, f2fma(fp, h2.y, f2mul(omfp, l2.y)), o0p[5]);
            o0p[6] = f2fma(g, f2fma(fp, h3.x, f2mul(omfp, l3.x)), o0p[6]);
            o0p[7] = f2fma(g, f2fma(fp, h3.y, f2mul(omfp, l3.y)), o0p[7]);
        }
        #pragma unroll
        for (int u = 0; u < 8; ++u) {
            ulonglong2 l0 = L[112 + u * 4], l1 = L[112 + u * 4 + 1],
                       l2 = L[112 + u * 4 + 2], l3 = L[112 + u * 4 + 3];
            ulonglong2 h0 = H[112 + u * 4], h1 = H[112 + u * 4 + 1],
                       h2 = H[112 + u * 4 + 2], h3 = H[112 + u * 4 + 3];
            ull g = pk2(dd[u]);
            o0p[0] = f2fma(g, f2fma(fp, h0.x, f2mul(omfp, l0.x)), o0p[0]);
            o0p[1] = f2fma(g, f2fma(fp, h0.y, f2mul(omfp, l0.y)), o0p[1]);
            o0p[2] = f2fma(g, f2fma(fp, h1.x, f2mul(omfp, l1.x)), o0p[2]);
            o0p[3] = f2fma(g, f2fma(fp, h1.y, f2mul(omfp, l1.y)), o0p[3]);
            o0p[4] = f2fma(g, f2fma(fp, h2.x, f2mul(omfp, l2.x)), o0p[4]);
            o0p[5] = f2fma(g, f2fma(fp, h2.y, f2mul(omfp, l2.y)), o0p[5]);
            o0p[6] = f2fma(g, f2fma(fp, h3.x, f2mul(omfp, l3.x)), o0p[6]);
            o0p[7] = f2fma(g, f2fma(fp, h3.y, f2mul(omfp, l3.y)), o0p[7]);
        }
        ull Ap[4];
        #pragma unroll
        for (int k = 0; k < 4; ++k) Ap[k] = pk2(0.f);
        #pragma unroll
        for (int u = 0; u < 16; ++u) {
            ulonglong2 l0 = L[64 + u * 2], l1 = L[64 + u * 2 + 1];
            ulonglong2 h0 = H[64 + u * 2], h1 = H[64 + u * 2 + 1];
            ull g = pk2(x0[u]);
            Ap[0] = f2fma(g, f2fma(fp, h0.x, f2mul(omfp, l0.x)), Ap[0]);
            Ap[1] = f2fma(g, f2fma(fp, h0.y, f2mul(omfp, l0.y)), Ap[1]);
            Ap[2] = f2fma(g, f2fma(fp, h1.x, f2mul(omfp, l1.x)), Ap[2]);
            Ap[3] = f2fma(g, f2fma(fp, h1.y, f2mul(omfp, l1.y)), Ap[3]);
        }
        float o1[24];
        #pragma unroll
        for (int k = 0; k < 24; ++k) o1[k] = 0.f;
        {
            const float4* mL = reinterpret_cast<const float4*>(sM + 1152 + 384);
            const float4* mH = mL + 144;
            #pragma unroll
            for (int u = 0; u < 8; ++u) {
                float4 AL = mL[u * 2], BL = mL[u * 2 + 1];
                float4 AH = mH[u * 2], BH = mH[u * 2 + 1];
                float m0 = fmaf(f, AH.x, omf * AL.x), m1 = fmaf(f, AH.y, omf * AL.y);
                float m2 = fmaf(f, AH.z, omf * AL.z), m3 = fmaf(f, AH.w, omf * AL.w);
                float m4 = fmaf(f, BH.x, omf * BL.x), m5 = fmaf(f, BH.y, omf * BL.y);
                float m6 = fmaf(f, BH.z, omf * BL.z), m7 = fmaf(f, BH.w, omf * BL.w);
                float xa = x1s[3 * u], xb = x1s[3 * u + 1], xc = x1s[3 * u + 2];
                o1[0] = fmaf(m0, xa, o1[0]);  o1[1] = fmaf(m0, xb, o1[1]);  o1[2] = fmaf(m0, xc, o1[2]);
                o1[3] = fmaf(m1, xa, o1[3]);  o1[4] = fmaf(m1, xb, o1[4]);  o1[5] = fmaf(m1, xc, o1[5]);
                o1[6] = fmaf(m2, xa, o1[6]);  o1[7] = fmaf(m2, xb, o1[7]);  o1[8] = fmaf(m2, xc, o1[8]);
                o1[9] = fmaf(m3, xa, o1[9]);  o1[10] = fmaf(m3, xb, o1[10]); o1[11] = fmaf(m3, xc, o1[11]);
                o1[12] = fmaf(m4, xa, o1[12]); o1[13] = fmaf(m4, xb, o1[13]); o1[14] = fmaf(m4, xc, o1[14]);
                o1[15] = fmaf(m5, xa, o1[15]); o1[16] = fmaf(m5, xb, o1[16]); o1[17] = fmaf(m5, xc, o1[17]);
                o1[18] = fmaf(m6, xa, o1[18]); o1[19] = fmaf(m6, xb, o1[19]); o1[20] = fmaf(m6, xc, o1[20]);
                o1[21] = fmaf(m7, xa, o1[21]); o1[22] = fmaf(m7, xb, o1[22]); o1[23] = fmaf(m7, xc, o1[23]);
            }
        }
        #pragma unroll
        for (int k = 0; k < 4; ++k) {
            float2 a2 = upk(Ap[k]);
            int w0 = 2 * k, w1 = 2 * k + 1;
            o1[3 * w0] = fmaf(a2.x, sh.y, o1[3 * w0]);
            o1[3 * w0 + 1] = fmaf(a2.x, sh.z, o1[3 * w0 + 1]);
            o1[3 * w0 + 2] = fmaf(a2.x, sh.w, o1[3 * w0 + 2]);
            o1[3 * w1] = fmaf(a2.y, sh.y, o1[3 * w1]);
            o1[3 * w1 + 1] = fmaf(a2.y, sh.z, o1[3 * w1 + 1]);
            o1[3 * w1 + 2] = fmaf(a2.y, sh.w, o1[3 * w1 + 2]);
        }

        // ---- vectorized scatter: 10 x red.v4
        float* ob = out + dst * 40;
        float o0[16];
        #pragma unroll
        for (int k = 0; k < 8; ++k) {
            float2 q = upk(o0p[k]);
            o0[2 * k] = q.x * fs;
            o0[2 * k + 1] = q.y * fs;
        }
        #pragma unroll
        for (int k = 0; k < 4; ++k)
            red4(ob + 4 * k, o0[4 * k], o0[4 * k + 1], o0[4 * k + 2], o0[4 * k + 3]);
        #pragma unroll
        for (int k = 0; k < 6; ++k)
            red4(ob + 16 + 4 * k, o1[4 * k] * fs, o1[4 * k + 1] * fs,
                 o1[4 * k + 2] * fs, o1[4 * k + 3] * fs);
    }
}

// -------- epilogue: out[i] *= rsqrt(z[i]); re-zero g_cnt for next launch
__global__ void normalize(float* __restrict__ out, int n) {
    int i = blockIdx.x * 128 + threadIdx.x;
    if (i < TBLM) g_cnt[i] = 0;
    if (i >= n) return;
    float zz = g_z[i];
    if (zz <= 0.f) zz = 1.f;
    float s = rsqrtf(zz);
    float4* o4 = reinterpret_cast<float4*>(out + i * 40);
    #pragma unroll
    for (int m = 0; m < 10; ++m) {
        float4 v = o4[m];
        v.x *= s; v.y *= s; v.z *= s; v.w *= s;
        o4[m] = v;
    }
}

extern "C" void kernel_launch(void* const* d_in, const int* in_sizes, int n_in,
                              void* d_out, int out_size) {
    const float* x   = (const float*)d_in[0];
    const int*   ei  = (const int*)d_in[1];
    const float* ea  = (const float*)d_in[2];
    const float* amf = (const float*)d_in[5];
    const float* Wq0 = (const float*)d_in[6];
    const float* Wq1 = (const float*)d_in[7];
    const float* Wk1 = (const float*)d_in[8];
    const float* Wk2 = (const float*)d_in[9];
    const float* Wv1 = (const float*)d_in[10];
    const float* Wv2 = (const float*)d_in[11];
    const float* Wd0 = (const float*)d_in[12];
    const float* Wd1 = (const float*)d_in[13];
    float* out = (float*)d_out;

    int n = in_sizes[0] / 40;
    int E = in_sizes[2] / 4;

    build_h_hist<<<(E + 255) / 256, 256>>>(Wk1, Wv1, amf, E);
    scan_kernel<<<1, 1024>>>(TBLM);
    int nbScat = (E + 255) / 256;
    int nbNode = (n + 255) / 256;
    int nbM = ((TBLM + 1) * 288 + 255) / 256;
    mega_kernel<<<nbScat + nbNode + nbM, 256>>>(
        x, ei, ea, amf, Wq0, Wq1, Wd0, Wd1, Wk2, Wv2, out, n, E, nbScat, nbNode);
    edge_fused<<<TBLM, 96>>>(x, out, E);
    normalize<<<(n + 127) / 128, 128>>>(out, n);
}